// round 1
// baseline (speedup 1.0000x reference)
#include <cuda_runtime.h>
#include <math.h>

#define Bn 16
#define Cc 32
#define Hh 128
#define Ww 128
#define HW (Hh*Ww)           // 16384
#define CHW (Cc*HW)          // 524288
#define NTOT (Bn*CHW)        // 8388608 elements per tensor

// Tile geometry: 8 rows x 32 cols per block, halo 10 x 34
#define TH 8
#define TW 32
#define HALO_H 10
#define HALO_W 34
#define TILE_ELEMS (HALO_H*HALO_W*Cc)   // 10880 floats

// Combined weights: [tensor(3)][ci*9+k (288)][co (64)]
__device__ float g_Wcomb[3*288*64];
__device__ float g_Wout[288*32];        // [ci*9+k][co]
__device__ float g_bcomb[64];
__device__ float g_bout[32];
__device__ float g_invtau[64];

__global__ void prep_kernel(
    const float* __restrict__ W_in_e, const float* __restrict__ b_in_e,
    const float* __restrict__ W_in_i, const float* __restrict__ b_in_i,
    const float* __restrict__ W_e_e,  const float* __restrict__ b_e_e,
    const float* __restrict__ W_e_i,  const float* __restrict__ b_e_i,
    const float* __restrict__ W_e_out,const float* __restrict__ b_e_out,
    const float* __restrict__ W_i_e,  const float* __restrict__ b_i_e,
    const float* __restrict__ W_i_i,  const float* __restrict__ b_i_i,
    const float* __restrict__ tau_e,  const float* __restrict__ tau_i)
{
    int fid = blockIdx.x * 256 + threadIdx.x;
    if (fid < 3*288*64) {
        int t    = fid / (288*64);
        int r    = fid % (288*64);
        int ci9k = r / 64;
        int co   = r % 64;
        int src  = (co & 31) * 288 + ci9k;   // OIHW: co*Cin*9 + ci*9 + k
        float w;
        if (t == 0) {
            w = (co < 32) ? W_in_e[src] : W_in_i[src];
        } else if (t == 1) {
            w = (co < 32) ? W_e_e[src] : W_e_i[src];
            w = fmaxf(w, 0.f);
        } else {
            w = (co < 32) ? W_i_e[src] : W_i_i[src];
            w = -fmaxf(w, 0.f);              // inhibitory: subtract
        }
        g_Wcomb[fid] = w;                    // layout matches fid exactly
    } else if (fid < 3*288*64 + 288*32) {
        int f2   = fid - 3*288*64;
        int co   = f2 % 32;
        int ci9k = f2 / 32;
        g_Wout[f2] = fmaxf(W_e_out[co*288 + ci9k], 0.f);
    }
    if (blockIdx.x == 0 && threadIdx.x < 64) {
        int co = threadIdx.x;
        if (co < 32) {
            g_bcomb[co]  = b_in_e[co] + fmaxf(b_e_e[co], 0.f) - fmaxf(b_i_e[co], 0.f);
            g_invtau[co] = 1.f / fmaxf(tau_e[co], 1.f);
            g_bout[co]   = fmaxf(b_e_out[co], 0.f);
        } else {
            int c = co - 32;
            g_bcomb[co]  = b_in_i[c] + fmaxf(b_e_i[c], 0.f) - fmaxf(b_i_i[c], 0.f);
            g_invtau[co] = 1.f / fmaxf(tau_i[c], 1.f);
        }
    }
}

// 6 fused convs -> cand_e/cand_i -> tanh -> leaky integrate -> h_e_new, h_i_new
__global__ void __launch_bounds__(256)
state_kernel(const float* __restrict__ x, const float* __restrict__ he,
             const float* __restrict__ hi, float* __restrict__ out)
{
    extern __shared__ float sm[];
    float* tile = sm;                 // TILE_ELEMS floats
    float* wsm  = sm + TILE_ELEMS;    // 288*64 floats

    const int tid = threadIdx.x;
    const int px  = tid & 31;
    const int py  = tid >> 5;
    const int b   = blockIdx.z;
    const int ty0 = blockIdx.y * TH;
    const int tx0 = blockIdx.x * TW;

    float acc[64];
    #pragma unroll
    for (int co = 0; co < 64; co++) acc[co] = g_bcomb[co];

    const float* srcs[3] = {x, he, hi};

    for (int t = 0; t < 3; t++) {
        // Stage per-tensor combined weights (co-contiguous for LDS.128 broadcast)
        const float* wg = g_Wcomb + t * (288*64);
        #pragma unroll 4
        for (int i = tid; i < 288*64; i += 256) wsm[i] = wg[i];

        // Stage input halo tile, zero-padded at the image border
        const float* src = srcs[t] + (size_t)b * CHW;
        for (int i = tid; i < TILE_ELEMS; i += 256) {
            int ci = i / (HALO_H*HALO_W);
            int r  = i - ci * (HALO_H*HALO_W);
            int yy = r / HALO_W;
            int xx = r - yy * HALO_W;
            int gy = ty0 + yy - 1;
            int gx = tx0 + xx - 1;
            float v = 0.f;
            if ((unsigned)gy < (unsigned)Hh && (unsigned)gx < (unsigned)Ww)
                v = src[ci*HW + gy*Ww + gx];
            tile[i] = v;
        }
        __syncthreads();

        for (int ci = 0; ci < 32; ci++) {
            const float* tp = tile + ci*(HALO_H*HALO_W) + py*HALO_W + px;
            const float4* wp = (const float4*)(wsm + ci*576);
            #pragma unroll
            for (int k = 0; k < 9; k++) {
                float v = tp[(k/3)*HALO_W + (k%3)];
                #pragma unroll
                for (int j = 0; j < 16; j++) {
                    float4 w = wp[k*16 + j];
                    acc[4*j+0] = fmaf(v, w.x, acc[4*j+0]);
                    acc[4*j+1] = fmaf(v, w.y, acc[4*j+1]);
                    acc[4*j+2] = fmaf(v, w.z, acc[4*j+2]);
                    acc[4*j+3] = fmaf(v, w.w, acc[4*j+3]);
                }
            }
        }
        __syncthreads();
    }

    // Epilogue: tanh + per-channel leaky integration
    const int gy = ty0 + py, gx = tx0 + px;
    const size_t pix = (size_t)b * CHW + (size_t)gy * Ww + gx;

    #pragma unroll
    for (int co = 0; co < 32; co++) {
        float c   = tanhf(acc[co]);
        float inv = g_invtau[co];
        float h   = he[pix + (size_t)co*HW];
        out[(size_t)NTOT + pix + (size_t)co*HW] = (1.f - inv)*h + inv*c;
    }
    #pragma unroll
    for (int co = 0; co < 32; co++) {
        float c   = tanhf(acc[co + 32]);
        float inv = g_invtau[co + 32];
        float h   = hi[pix + (size_t)co*HW];
        out[(size_t)2*NTOT + pix + (size_t)co*HW] = (1.f - inv)*h + inv*c;
    }
}

// out = tanh(conv(h_e_new, relu(W_e_out)) + relu(b_e_out))
__global__ void __launch_bounds__(256)
out_kernel(const float* __restrict__ hen, float* __restrict__ out)
{
    extern __shared__ float sm[];
    float* tile = sm;                 // TILE_ELEMS floats
    float* wsm  = sm + TILE_ELEMS;    // 288*32 floats

    const int tid = threadIdx.x;
    const int px  = tid & 31;
    const int py  = tid >> 5;
    const int b   = blockIdx.z;
    const int ty0 = blockIdx.y * TH;
    const int tx0 = blockIdx.x * TW;

    float acc[32];
    #pragma unroll
    for (int co = 0; co < 32; co++) acc[co] = g_bout[co];

    #pragma unroll 4
    for (int i = tid; i < 288*32; i += 256) wsm[i] = g_Wout[i];

    const float* src = hen + (size_t)b * CHW;
    for (int i = tid; i < TILE_ELEMS; i += 256) {
        int ci = i / (HALO_H*HALO_W);
        int r  = i - ci * (HALO_H*HALO_W);
        int yy = r / HALO_W;
        int xx = r - yy * HALO_W;
        int gy = ty0 + yy - 1;
        int gx = tx0 + xx - 1;
        float v = 0.f;
        if ((unsigned)gy < (unsigned)Hh && (unsigned)gx < (unsigned)Ww)
            v = src[ci*HW + gy*Ww + gx];
        tile[i] = v;
    }
    __syncthreads();

    for (int ci = 0; ci < 32; ci++) {
        const float* tp = tile + ci*(HALO_H*HALO_W) + py*HALO_W + px;
        const float4* wp = (const float4*)(wsm + ci*288);
        #pragma unroll
        for (int k = 0; k < 9; k++) {
            float v = tp[(k/3)*HALO_W + (k%3)];
            #pragma unroll
            for (int j = 0; j < 8; j++) {
                float4 w = wp[k*8 + j];
                acc[4*j+0] = fmaf(v, w.x, acc[4*j+0]);
                acc[4*j+1] = fmaf(v, w.y, acc[4*j+1]);
                acc[4*j+2] = fmaf(v, w.z, acc[4*j+2]);
                acc[4*j+3] = fmaf(v, w.w, acc[4*j+3]);
            }
        }
    }

    const int gy = ty0 + py, gx = tx0 + px;
    const size_t pix = (size_t)b * CHW + (size_t)gy * Ww + gx;
    #pragma unroll
    for (int co = 0; co < 32; co++)
        out[pix + (size_t)co*HW] = tanhf(acc[co]);
}

extern "C" void kernel_launch(void* const* d_in, const int* in_sizes, int n_in,
                              void* d_out, int out_size)
{
    (void)in_sizes; (void)n_in; (void)out_size;
    const float* x  = (const float*)d_in[0];
    const float* he = (const float*)d_in[1];
    const float* hi = (const float*)d_in[2];
    float* out = (float*)d_out;

    const int state_smem = (TILE_ELEMS + 288*64) * 4;   // 117248 B
    const int out_smem   = (TILE_ELEMS + 288*32) * 4;   // 80384 B
    cudaFuncSetAttribute(state_kernel, cudaFuncAttributeMaxDynamicSharedMemorySize, state_smem);
    cudaFuncSetAttribute(out_kernel,   cudaFuncAttributeMaxDynamicSharedMemorySize, out_smem);

    // Weight / bias preprocessing (covers 3*288*64 + 288*32 = 64512 elements)
    prep_kernel<<<252, 256>>>(
        (const float*)d_in[3],  (const float*)d_in[4],   // W_in_e, b_in_e
        (const float*)d_in[5],  (const float*)d_in[6],   // W_in_i, b_in_i
        (const float*)d_in[7],  (const float*)d_in[8],   // W_e_e,  b_e_e
        (const float*)d_in[9],  (const float*)d_in[10],  // W_e_i,  b_e_i
        (const float*)d_in[11], (const float*)d_in[12],  // W_e_out,b_e_out
        (const float*)d_in[13], (const float*)d_in[14],  // W_i_e,  b_i_e
        (const float*)d_in[15], (const float*)d_in[16],  // W_i_i,  b_i_i
        (const float*)d_in[17], (const float*)d_in[18]); // tau_e,  tau_i

    dim3 grid(Ww/TW, Hh/TH, Bn);   // (4, 16, 16)
    state_kernel<<<grid, 256, state_smem>>>(x, he, hi, out);
    // h_e_new lives at out + NTOT
    out_kernel<<<grid, 256, out_smem>>>(out + NTOT, out);
}

// round 2
// speedup vs baseline: 1.0310x; 1.0310x over previous
#include <cuda_runtime.h>
#include <math.h>
#include <stdint.h>

#define Bn 16
#define Cc 32
#define Hh 128
#define Ww 128
#define HW (Hh*Ww)           // 16384
#define CHW (Cc*HW)          // 524288
#define NTOT (Bn*CHW)        // 8388608 elements per tensor

// Tile geometry: 8 rows x 32 cols per block, halo 10 x 34
#define TH 8
#define TW 32
#define HALO_H 10
#define HALO_W 34
#define TILE_ELEMS (HALO_H*HALO_W*Cc)   // 10880 floats

// Combined weights: [tensor(3)][ci*9+k (288)][co (64)]
__device__ float g_Wcomb[3*288*64];
__device__ float g_Wout[288*32];        // [ci*9+k][co]
__device__ float g_bcomb[64];
__device__ float g_bout[32];
__device__ float g_invtau[64];

// ---- packed f32x2 helpers (FFMA2: 2 fp32 FMAs per issue slot) ----
__device__ __forceinline__ uint64_t pack_dup(float v) {
    uint64_t r;
    asm("mov.b64 %0, {%1, %1};" : "=l"(r) : "r"(__float_as_uint(v)));
    return r;
}
__device__ __forceinline__ void fma2(uint64_t& acc, uint64_t a, uint64_t b) {
    asm("fma.rn.f32x2 %0, %1, %2, %0;" : "+l"(acc) : "l"(a), "l"(b));
}
__device__ __forceinline__ void unpack2(uint64_t p, float& lo, float& hi) {
    uint32_t l, h;
    asm("mov.b64 {%0, %1}, %2;" : "=r"(l), "=r"(h) : "l"(p));
    lo = __uint_as_float(l); hi = __uint_as_float(h);
}

__global__ void prep_kernel(
    const float* __restrict__ W_in_e, const float* __restrict__ b_in_e,
    const float* __restrict__ W_in_i, const float* __restrict__ b_in_i,
    const float* __restrict__ W_e_e,  const float* __restrict__ b_e_e,
    const float* __restrict__ W_e_i,  const float* __restrict__ b_e_i,
    const float* __restrict__ W_e_out,const float* __restrict__ b_e_out,
    const float* __restrict__ W_i_e,  const float* __restrict__ b_i_e,
    const float* __restrict__ W_i_i,  const float* __restrict__ b_i_i,
    const float* __restrict__ tau_e,  const float* __restrict__ tau_i)
{
    int fid = blockIdx.x * 256 + threadIdx.x;
    if (fid < 3*288*64) {
        int t    = fid / (288*64);
        int r    = fid % (288*64);
        int ci9k = r / 64;
        int co   = r % 64;
        int src  = (co & 31) * 288 + ci9k;   // OIHW: co*Cin*9 + ci*9 + k
        float w;
        if (t == 0) {
            w = (co < 32) ? W_in_e[src] : W_in_i[src];
        } else if (t == 1) {
            w = (co < 32) ? W_e_e[src] : W_e_i[src];
            w = fmaxf(w, 0.f);
        } else {
            w = (co < 32) ? W_i_e[src] : W_i_i[src];
            w = -fmaxf(w, 0.f);              // inhibitory: subtract
        }
        g_Wcomb[fid] = w;
    } else if (fid < 3*288*64 + 288*32) {
        int f2   = fid - 3*288*64;
        int co   = f2 % 32;
        int ci9k = f2 / 32;
        g_Wout[f2] = fmaxf(W_e_out[co*288 + ci9k], 0.f);
    }
    if (blockIdx.x == 0 && threadIdx.x < 64) {
        int co = threadIdx.x;
        if (co < 32) {
            g_bcomb[co]  = b_in_e[co] + fmaxf(b_e_e[co], 0.f) - fmaxf(b_i_e[co], 0.f);
            g_invtau[co] = 1.f / fmaxf(tau_e[co], 1.f);
            g_bout[co]   = fmaxf(b_e_out[co], 0.f);
        } else {
            int c = co - 32;
            g_bcomb[co]  = b_in_i[c] + fmaxf(b_e_i[c], 0.f) - fmaxf(b_i_i[c], 0.f);
            g_invtau[co] = 1.f / fmaxf(tau_i[c], 1.f);
        }
    }
}

// 6 fused convs -> cand_e/cand_i -> tanh -> leaky integrate -> h_e_new, h_i_new
__global__ void __launch_bounds__(256)
state_kernel(const float* __restrict__ x, const float* __restrict__ he,
             const float* __restrict__ hi, float* __restrict__ out)
{
    extern __shared__ float sm[];
    float* tile = sm;                 // TILE_ELEMS floats
    float* wsm  = sm + TILE_ELEMS;    // 288*64 floats

    const int tid = threadIdx.x;
    const int px  = tid & 31;
    const int py  = tid >> 5;
    const int b   = blockIdx.z;
    const int ty0 = blockIdx.y * TH;
    const int tx0 = blockIdx.x * TW;

    // 64 fp32 accumulators packed into 32 f32x2 registers; pair (2j, 2j+1)
    uint64_t acc2[32];
    #pragma unroll
    for (int j = 0; j < 32; j++) {
        uint32_t l = __float_as_uint(g_bcomb[2*j]);
        uint32_t h = __float_as_uint(g_bcomb[2*j+1]);
        asm("mov.b64 %0, {%1, %2};" : "=l"(acc2[j]) : "r"(l), "r"(h));
    }

    const float* srcs[3] = {x, he, hi};

    for (int t = 0; t < 3; t++) {
        // Stage per-tensor combined weights (co-contiguous, 16B-aligned pairs)
        const float* wg = g_Wcomb + t * (288*64);
        #pragma unroll 4
        for (int i = tid; i < 288*64; i += 256) wsm[i] = wg[i];

        // Stage input halo tile, zero-padded at image border
        const float* src = srcs[t] + (size_t)b * CHW;
        for (int i = tid; i < TILE_ELEMS; i += 256) {
            int ci = i / (HALO_H*HALO_W);
            int r  = i - ci * (HALO_H*HALO_W);
            int yy = r / HALO_W;
            int xx = r - yy * HALO_W;
            int gy = ty0 + yy - 1;
            int gx = tx0 + xx - 1;
            float v = 0.f;
            if ((unsigned)gy < (unsigned)Hh && (unsigned)gx < (unsigned)Ww)
                v = src[ci*HW + gy*Ww + gx];
            tile[i] = v;
        }
        __syncthreads();

        for (int ci = 0; ci < 32; ci++) {
            const float* tp = tile + ci*(HALO_H*HALO_W) + py*HALO_W + px;
            const ulonglong2* wp = (const ulonglong2*)(wsm + ci*576);
            #pragma unroll
            for (int k = 0; k < 9; k++) {
                uint64_t vv = pack_dup(tp[(k/3)*HALO_W + (k%3)]);
                #pragma unroll
                for (int j = 0; j < 16; j++) {
                    ulonglong2 w = wp[k*16 + j];   // LDS.128 broadcast: 4 weights
                    fma2(acc2[2*j],   vv, w.x);
                    fma2(acc2[2*j+1], vv, w.y);
                }
            }
        }
        __syncthreads();
    }

    // Epilogue: tanh + per-channel leaky integration
    const int gy = ty0 + py, gx = tx0 + px;
    const size_t pix = (size_t)b * CHW + (size_t)gy * Ww + gx;

    #pragma unroll
    for (int j = 0; j < 16; j++) {           // co = 2j, 2j+1 (excitatory)
        float a0, a1;
        unpack2(acc2[j], a0, a1);
        int c0 = 2*j, c1 = 2*j + 1;
        float i0 = g_invtau[c0], i1 = g_invtau[c1];
        float h0 = he[pix + (size_t)c0*HW], h1 = he[pix + (size_t)c1*HW];
        out[(size_t)NTOT + pix + (size_t)c0*HW] = (1.f - i0)*h0 + i0*tanhf(a0);
        out[(size_t)NTOT + pix + (size_t)c1*HW] = (1.f - i1)*h1 + i1*tanhf(a1);
    }
    #pragma unroll
    for (int j = 16; j < 32; j++) {          // co = 2j-32 .. (inhibitory)
        float a0, a1;
        unpack2(acc2[j], a0, a1);
        int c0 = 2*j - 32, c1 = 2*j - 31;
        float i0 = g_invtau[c0 + 32], i1 = g_invtau[c1 + 32];
        float h0 = hi[pix + (size_t)c0*HW], h1 = hi[pix + (size_t)c1*HW];
        out[(size_t)2*NTOT + pix + (size_t)c0*HW] = (1.f - i0)*h0 + i0*tanhf(a0);
        out[(size_t)2*NTOT + pix + (size_t)c1*HW] = (1.f - i1)*h1 + i1*tanhf(a1);
    }
}

// out = tanh(conv(h_e_new, relu(W_e_out)) + relu(b_e_out))
__global__ void __launch_bounds__(256)
out_kernel(const float* __restrict__ hen, float* __restrict__ out)
{
    extern __shared__ float sm[];
    float* tile = sm;                 // TILE_ELEMS floats
    float* wsm  = sm + TILE_ELEMS;    // 288*32 floats

    const int tid = threadIdx.x;
    const int px  = tid & 31;
    const int py  = tid >> 5;
    const int b   = blockIdx.z;
    const int ty0 = blockIdx.y * TH;
    const int tx0 = blockIdx.x * TW;

    uint64_t acc2[16];
    #pragma unroll
    for (int j = 0; j < 16; j++) {
        uint32_t l = __float_as_uint(g_bout[2*j]);
        uint32_t h = __float_as_uint(g_bout[2*j+1]);
        asm("mov.b64 %0, {%1, %2};" : "=l"(acc2[j]) : "r"(l), "r"(h));
    }

    #pragma unroll 4
    for (int i = tid; i < 288*32; i += 256) wsm[i] = g_Wout[i];

    const float* src = hen + (size_t)b * CHW;
    for (int i = tid; i < TILE_ELEMS; i += 256) {
        int ci = i / (HALO_H*HALO_W);
        int r  = i - ci * (HALO_H*HALO_W);
        int yy = r / HALO_W;
        int xx = r - yy * HALO_W;
        int gy = ty0 + yy - 1;
        int gx = tx0 + xx - 1;
        float v = 0.f;
        if ((unsigned)gy < (unsigned)Hh && (unsigned)gx < (unsigned)Ww)
            v = src[ci*HW + gy*Ww + gx];
        tile[i] = v;
    }
    __syncthreads();

    for (int ci = 0; ci < 32; ci++) {
        const float* tp = tile + ci*(HALO_H*HALO_W) + py*HALO_W + px;
        const ulonglong2* wp = (const ulonglong2*)(wsm + ci*288);
        #pragma unroll
        for (int k = 0; k < 9; k++) {
            uint64_t vv = pack_dup(tp[(k/3)*HALO_W + (k%3)]);
            #pragma unroll
            for (int j = 0; j < 8; j++) {
                ulonglong2 w = wp[k*8 + j];
                fma2(acc2[2*j],   vv, w.x);
                fma2(acc2[2*j+1], vv, w.y);
            }
        }
    }

    const int gy = ty0 + py, gx = tx0 + px;
    const size_t pix = (size_t)b * CHW + (size_t)gy * Ww + gx;
    #pragma unroll
    for (int j = 0; j < 16; j++) {
        float a0, a1;
        unpack2(acc2[j], a0, a1);
        out[pix + (size_t)(2*j)*HW]   = tanhf(a0);
        out[pix + (size_t)(2*j+1)*HW] = tanhf(a1);
    }
}

extern "C" void kernel_launch(void* const* d_in, const int* in_sizes, int n_in,
                              void* d_out, int out_size)
{
    (void)in_sizes; (void)n_in; (void)out_size;
    const float* x  = (const float*)d_in[0];
    const float* he = (const float*)d_in[1];
    const float* hi = (const float*)d_in[2];
    float* out = (float*)d_out;

    const int state_smem = (TILE_ELEMS + 288*64) * 4;   // 117248 B
    const int out_smem   = (TILE_ELEMS + 288*32) * 4;   // 80384 B
    cudaFuncSetAttribute(state_kernel, cudaFuncAttributeMaxDynamicSharedMemorySize, state_smem);
    cudaFuncSetAttribute(out_kernel,   cudaFuncAttributeMaxDynamicSharedMemorySize, out_smem);

    prep_kernel<<<252, 256>>>(
        (const float*)d_in[3],  (const float*)d_in[4],   // W_in_e, b_in_e
        (const float*)d_in[5],  (const float*)d_in[6],   // W_in_i, b_in_i
        (const float*)d_in[7],  (const float*)d_in[8],   // W_e_e,  b_e_e
        (const float*)d_in[9],  (const float*)d_in[10],  // W_e_i,  b_e_i
        (const float*)d_in[11], (const float*)d_in[12],  // W_e_out,b_e_out
        (const float*)d_in[13], (const float*)d_in[14],  // W_i_e,  b_i_e
        (const float*)d_in[15], (const float*)d_in[16],  // W_i_i,  b_i_i
        (const float*)d_in[17], (const float*)d_in[18]); // tau_e,  tau_i

    dim3 grid(Ww/TW, Hh/TH, Bn);   // (4, 16, 16)
    state_kernel<<<grid, 256, state_smem>>>(x, he, hi, out);
    out_kernel<<<grid, 256, out_smem>>>(out + NTOT, out);
}

// round 3
// speedup vs baseline: 1.0441x; 1.0127x over previous
#include <cuda_runtime.h>
#include <math.h>
#include <stdint.h>

#define Bn 16
#define Cc 32
#define Hh 128
#define Ww 128
#define HW (Hh*Ww)           // 16384
#define CHW (Cc*HW)          // 524288
#define NTOT (Bn*CHW)        // 8388608 elements per tensor

// Tile geometry: 8 rows x 32 cols per block, halo 10 x 34
#define TH 8
#define TW 32
#define HALO_H 10
#define HALO_W 34
#define TILE_ELEMS (HALO_H*HALO_W*Cc)   // 10880 floats

// Combined weights: [tensor(3)][ci*9+k (288)][co (64)]
__device__ float g_Wcomb[3*288*64];
__device__ float g_Wout[288*32];        // [ci*9+k][co]
__device__ float g_bcomb[64];
__device__ float g_bout[32];
__device__ float g_invtau[64];

// ---- packed f32x2 helpers (FFMA2: 2 fp32 FMAs per issue slot) ----
__device__ __forceinline__ uint64_t pack_dup(float v) {
    uint64_t r;
    asm("mov.b64 %0, {%1, %1};" : "=l"(r) : "r"(__float_as_uint(v)));
    return r;
}
__device__ __forceinline__ void fma2(uint64_t& acc, uint64_t a, uint64_t b) {
    asm("fma.rn.f32x2 %0, %1, %2, %0;" : "+l"(acc) : "l"(a), "l"(b));
}
__device__ __forceinline__ void unpack2(uint64_t p, float& lo, float& hi) {
    uint32_t l, h;
    asm("mov.b64 {%0, %1}, %2;" : "=r"(l), "=r"(h) : "l"(p));
    lo = __uint_as_float(l); hi = __uint_as_float(h);
}

__global__ void prep_kernel(
    const float* __restrict__ W_in_e, const float* __restrict__ b_in_e,
    const float* __restrict__ W_in_i, const float* __restrict__ b_in_i,
    const float* __restrict__ W_e_e,  const float* __restrict__ b_e_e,
    const float* __restrict__ W_e_i,  const float* __restrict__ b_e_i,
    const float* __restrict__ W_e_out,const float* __restrict__ b_e_out,
    const float* __restrict__ W_i_e,  const float* __restrict__ b_i_e,
    const float* __restrict__ W_i_i,  const float* __restrict__ b_i_i,
    const float* __restrict__ tau_e,  const float* __restrict__ tau_i)
{
    int fid = blockIdx.x * 256 + threadIdx.x;
    if (fid < 3*288*64) {
        int t    = fid / (288*64);
        int r    = fid % (288*64);
        int ci9k = r / 64;
        int co   = r % 64;
        int src  = (co & 31) * 288 + ci9k;   // OIHW: co*Cin*9 + ci*9 + k
        float w;
        if (t == 0) {
            w = (co < 32) ? W_in_e[src] : W_in_i[src];
        } else if (t == 1) {
            w = (co < 32) ? W_e_e[src] : W_e_i[src];
            w = fmaxf(w, 0.f);
        } else {
            w = (co < 32) ? W_i_e[src] : W_i_i[src];
            w = -fmaxf(w, 0.f);              // inhibitory: subtract
        }
        g_Wcomb[fid] = w;
    } else if (fid < 3*288*64 + 288*32) {
        int f2   = fid - 3*288*64;
        int co   = f2 % 32;
        int ci9k = f2 / 32;
        g_Wout[f2] = fmaxf(W_e_out[co*288 + ci9k], 0.f);
    }
    if (blockIdx.x == 0 && threadIdx.x < 64) {
        int co = threadIdx.x;
        if (co < 32) {
            g_bcomb[co]  = b_in_e[co] + fmaxf(b_e_e[co], 0.f) - fmaxf(b_i_e[co], 0.f);
            g_invtau[co] = 1.f / fmaxf(tau_e[co], 1.f);
            g_bout[co]   = fmaxf(b_e_out[co], 0.f);
        } else {
            int c = co - 32;
            g_bcomb[co]  = b_in_i[c] + fmaxf(b_e_i[c], 0.f) - fmaxf(b_i_i[c], 0.f);
            g_invtau[co] = 1.f / fmaxf(tau_i[c], 1.f);
        }
    }
}

// 6 fused convs -> cand_e/cand_i -> tanh -> leaky integrate -> h_e_new, h_i_new
__global__ void __launch_bounds__(256)
state_kernel(const float* __restrict__ x, const float* __restrict__ he,
             const float* __restrict__ hi, float* __restrict__ out)
{
    extern __shared__ float sm[];
    float* tile = sm;                 // TILE_ELEMS floats
    float* wsm  = sm + TILE_ELEMS;    // 288*64 floats

    const int tid = threadIdx.x;
    const int px  = tid & 31;
    const int py  = tid >> 5;
    const int b   = blockIdx.z;
    const int ty0 = blockIdx.y * TH;
    const int tx0 = blockIdx.x * TW;

    // 64 fp32 accumulators packed into 32 f32x2 registers; pair (2j, 2j+1)
    uint64_t acc2[32];
    #pragma unroll
    for (int j = 0; j < 32; j++) {
        uint32_t l = __float_as_uint(g_bcomb[2*j]);
        uint32_t h = __float_as_uint(g_bcomb[2*j+1]);
        asm("mov.b64 %0, {%1, %2};" : "=l"(acc2[j]) : "r"(l), "r"(h));
    }

    const float* srcs[3] = {x, he, hi};

    for (int t = 0; t < 3; t++) {
        // Stage per-tensor combined weights (co-contiguous, 16B-aligned pairs)
        const float* wg = g_Wcomb + t * (288*64);
        #pragma unroll 4
        for (int i = tid; i < 288*64; i += 256) wsm[i] = wg[i];

        // Stage input halo tile, zero-padded at image border
        const float* src = srcs[t] + (size_t)b * CHW;
        for (int i = tid; i < TILE_ELEMS; i += 256) {
            int ci = i / (HALO_H*HALO_W);
            int r  = i - ci * (HALO_H*HALO_W);
            int yy = r / HALO_W;
            int xx = r - yy * HALO_W;
            int gy = ty0 + yy - 1;
            int gx = tx0 + xx - 1;
            float v = 0.f;
            if ((unsigned)gy < (unsigned)Hh && (unsigned)gx < (unsigned)Ww)
                v = src[ci*HW + gy*Ww + gx];
            tile[i] = v;
        }
        __syncthreads();

        for (int ci = 0; ci < 32; ci++) {
            const float* tp = tile + ci*(HALO_H*HALO_W) + py*HALO_W + px;
            const ulonglong2* wp = (const ulonglong2*)(wsm + ci*576);
            #pragma unroll
            for (int k = 0; k < 9; k++) {
                uint64_t vv = pack_dup(tp[(k/3)*HALO_W + (k%3)]);
                #pragma unroll
                for (int j = 0; j < 16; j++) {
                    ulonglong2 w = wp[k*16 + j];   // LDS.128 broadcast: 4 weights
                    fma2(acc2[2*j],   vv, w.x);
                    fma2(acc2[2*j+1], vv, w.y);
                }
            }
        }
        __syncthreads();
    }

    // Epilogue: tanh + per-channel leaky integration
    const int gy = ty0 + py, gx = tx0 + px;
    const size_t pix = (size_t)b * CHW + (size_t)gy * Ww + gx;

    #pragma unroll
    for (int j = 0; j < 16; j++) {           // co = 2j, 2j+1 (excitatory)
        float a0, a1;
        unpack2(acc2[j], a0, a1);
        int c0 = 2*j, c1 = 2*j + 1;
        float i0 = g_invtau[c0], i1 = g_invtau[c1];
        float h0 = he[pix + (size_t)c0*HW], h1 = he[pix + (size_t)c1*HW];
        out[(size_t)NTOT + pix + (size_t)c0*HW] = (1.f - i0)*h0 + i0*tanhf(a0);
        out[(size_t)NTOT + pix + (size_t)c1*HW] = (1.f - i1)*h1 + i1*tanhf(a1);
    }
    #pragma unroll
    for (int j = 16; j < 32; j++) {          // co = 2j-32 .. (inhibitory)
        float a0, a1;
        unpack2(acc2[j], a0, a1);
        int c0 = 2*j - 32, c1 = 2*j - 31;
        float i0 = g_invtau[c0 + 32], i1 = g_invtau[c1 + 32];
        float h0 = hi[pix + (size_t)c0*HW], h1 = hi[pix + (size_t)c1*HW];
        out[(size_t)2*NTOT + pix + (size_t)c0*HW] = (1.f - i0)*h0 + i0*tanhf(a0);
        out[(size_t)2*NTOT + pix + (size_t)c1*HW] = (1.f - i1)*h1 + i1*tanhf(a1);
    }
}

// out = tanh(conv(h_e_new, relu(W_e_out)) + relu(b_e_out))
__global__ void __launch_bounds__(256)
out_kernel(const float* __restrict__ hen, float* __restrict__ out)
{
    extern __shared__ float sm[];
    float* tile = sm;                 // TILE_ELEMS floats
    float* wsm  = sm + TILE_ELEMS;    // 288*32 floats

    const int tid = threadIdx.x;
    const int px  = tid & 31;
    const int py  = tid >> 5;
    const int b   = blockIdx.z;
    const int ty0 = blockIdx.y * TH;
    const int tx0 = blockIdx.x * TW;

    uint64_t acc2[16];
    #pragma unroll
    for (int j = 0; j < 16; j++) {
        uint32_t l = __float_as_uint(g_bout[2*j]);
        uint32_t h = __float_as_uint(g_bout[2*j+1]);
        asm("mov.b64 %0, {%1, %2};" : "=l"(acc2[j]) : "r"(l), "r"(h));
    }

    #pragma unroll 4
    for (int i = tid; i < 288*32; i += 256) wsm[i] = g_Wout[i];

    const float* src = hen + (size_t)b * CHW;
    for (int i = tid; i < TILE_ELEMS; i += 256) {
        int ci = i / (HALO_H*HALO_W);
        int r  = i - ci * (HALO_H*HALO_W);
        int yy = r / HALO_W;
        int xx = r - yy * HALO_W;
        int gy = ty0 + yy - 1;
        int gx = tx0 + xx - 1;
        float v = 0.f;
        if ((unsigned)gy < (unsigned)Hh && (unsigned)gx < (unsigned)Ww)
            v = src[ci*HW + gy*Ww + gx];
        tile[i] = v;
    }
    __syncthreads();

    for (int ci = 0; ci < 32; ci++) {
        const float* tp = tile + ci*(HALO_H*HALO_W) + py*HALO_W + px;
        const ulonglong2* wp = (const ulonglong2*)(wsm + ci*288);
        #pragma unroll
        for (int k = 0; k < 9; k++) {
            uint64_t vv = pack_dup(tp[(k/3)*HALO_W + (k%3)]);
            #pragma unroll
            for (int j = 0; j < 8; j++) {
                ulonglong2 w = wp[k*8 + j];
                fma2(acc2[2*j],   vv, w.x);
                fma2(acc2[2*j+1], vv, w.y);
            }
        }
    }

    const int gy = ty0 + py, gx = tx0 + px;
    const size_t pix = (size_t)b * CHW + (size_t)gy * Ww + gx;
    #pragma unroll
    for (int j = 0; j < 16; j++) {
        float a0, a1;
        unpack2(acc2[j], a0, a1);
        out[pix + (size_t)(2*j)*HW]   = tanhf(a0);
        out[pix + (size_t)(2*j+1)*HW] = tanhf(a1);
    }
}

extern "C" void kernel_launch(void* const* d_in, const int* in_sizes, int n_in,
                              void* d_out, int out_size)
{
    (void)in_sizes; (void)n_in; (void)out_size;
    const float* x  = (const float*)d_in[0];
    const float* he = (const float*)d_in[1];
    const float* hi = (const float*)d_in[2];
    float* out = (float*)d_out;

    const int state_smem = (TILE_ELEMS + 288*64) * 4;   // 117248 B
    const int out_smem   = (TILE_ELEMS + 288*32) * 4;   // 80384 B
    cudaFuncSetAttribute(state_kernel, cudaFuncAttributeMaxDynamicSharedMemorySize, state_smem);
    cudaFuncSetAttribute(out_kernel,   cudaFuncAttributeMaxDynamicSharedMemorySize, out_smem);

    prep_kernel<<<252, 256>>>(
        (const float*)d_in[3],  (const float*)d_in[4],   // W_in_e, b_in_e
        (const float*)d_in[5],  (const float*)d_in[6],   // W_in_i, b_in_i
        (const float*)d_in[7],  (const float*)d_in[8],   // W_e_e,  b_e_e
        (const float*)d_in[9],  (const float*)d_in[10],  // W_e_i,  b_e_i
        (const float*)d_in[11], (const float*)d_in[12],  // W_e_out,b_e_out
        (const float*)d_in[13], (const float*)d_in[14],  // W_i_e,  b_i_e
        (const float*)d_in[15], (const float*)d_in[16],  // W_i_i,  b_i_i
        (const float*)d_in[17], (const float*)d_in[18]); // tau_e,  tau_i

    dim3 grid(Ww/TW, Hh/TH, Bn);   // (4, 16, 16)
    state_kernel<<<grid, 256, state_smem>>>(x, he, hi, out);
    out_kernel<<<grid, 256, out_smem>>>(out + NTOT, out);
}

// round 5
// speedup vs baseline: 3.7656x; 3.6067x over previous
#include <cuda_runtime.h>
#include <math.h>
#include <stdint.h>

#define Bn 16
#define Cc 32
#define Hh 128
#define Ww 128
#define HW (Hh*Ww)
#define CHW (Cc*HW)
#define NTOT (Bn*CHW)

// block tile: 8 out rows x 32 out cols = 256 px; halo 10x34 = 340 A rows
#define NROWS 340

// state kernel SMEM: B (9 taps x 64 co x 128B) then A (340 x 128B)
#define ST_B_OFF 0
#define ST_B_SZ  73728
#define ST_A_OFF ST_B_SZ
#define A_SZ     (NROWS*128)
#define ST_SMEM  (ST_B_SZ + A_SZ)        // 117,248 B
// out kernel SMEM
#define OU_B_OFF 0
#define OU_B_SZ  36864
#define OU_A_OFF OU_B_SZ
#define OU_SMEM  (OU_B_SZ + A_SZ)        // 80,384 B

__device__ __align__(16) unsigned short g_Bst[3*36864];  // 3 x 73728 B, pre-swizzled
__device__ __align__(16) unsigned short g_Bout[18432];   // 36864 B, pre-swizzled
__device__ float g_bcomb[64];
__device__ float g_bout[32];
__device__ float g_invtau[64];

// ---------------- helpers ----------------
__device__ __forceinline__ void bf16split(float v, unsigned short& h, unsigned short& l) {
    asm("cvt.rn.bf16.f32 %0, %1;" : "=h"(h) : "f"(v));
    float hf;
    asm("cvt.f32.bf16 %0, %1;" : "=f"(hf) : "h"(h));
    asm("cvt.rn.bf16.f32 %0, %1;" : "=h"(l) : "f"(v - hf));
}
__device__ __forceinline__ float fast_tanh(float x) {
    float e, r;
    asm("ex2.approx.f32 %0, %1;" : "=f"(e) : "f"(x * 2.8853900817779268f)); // e^{2x}
    asm("rcp.approx.f32 %0, %1;" : "=f"(r) : "f"(e + 1.f));
    return fmaf(-2.f, r, 1.f);
}
__device__ __forceinline__ void mma16816(float* c,
    uint32_t a0, uint32_t a1, uint32_t a2, uint32_t a3, uint32_t b0, uint32_t b1)
{
    asm volatile(
        "mma.sync.aligned.m16n8k16.row.col.f32.bf16.bf16.f32 "
        "{%0,%1,%2,%3}, {%4,%5,%6,%7}, {%8,%9}, {%0,%1,%2,%3};"
        : "+f"(c[0]), "+f"(c[1]), "+f"(c[2]), "+f"(c[3])
        : "r"(a0), "r"(a1), "r"(a2), "r"(a3), "r"(b0), "r"(b1));
}
__device__ __forceinline__ uint32_t lds32(const char* sm, uint32_t off) {
    return *(const uint32_t*)(sm + off);
}

// split-precision pass schedule (byte offsets into 128B rows)
// pass1: A.hi x W.hi  | pass2: A.lo x W.hi | pass3: A.hi x W.lo
__device__ __constant__ int c_aoffB[6] = {0, 32, 64, 96, 0, 32};
__device__ __constant__ int c_boffB[6] = {0, 32, 0, 32, 64, 96};

// ---------------- prep: fold Dale rectify/sign, bf16 hi/lo split, pre-swizzle ----------------
__global__ void prep_kernel(
    const float* __restrict__ W_in_e, const float* __restrict__ b_in_e,
    const float* __restrict__ W_in_i, const float* __restrict__ b_in_i,
    const float* __restrict__ W_e_e,  const float* __restrict__ b_e_e,
    const float* __restrict__ W_e_i,  const float* __restrict__ b_e_i,
    const float* __restrict__ W_e_out,const float* __restrict__ b_e_out,
    const float* __restrict__ W_i_e,  const float* __restrict__ b_i_e,
    const float* __restrict__ W_i_i,  const float* __restrict__ b_i_i,
    const float* __restrict__ tau_e,  const float* __restrict__ tau_i)
{
    int fid = blockIdx.x * 256 + threadIdx.x;
    if (fid < 3*9*64*32) {
        int ci  = fid & 31;
        int r   = fid >> 5;
        int co  = r & 63;  r >>= 6;
        int tau = r % 9;
        int t   = r / 9;
        int src = (co & 31) * 288 + ci * 9 + tau;   // OIHW
        float w;
        if (t == 0)      w = (co < 32) ? W_in_e[src] : W_in_i[src];
        else if (t == 1) w = fmaxf((co < 32) ? W_e_e[src] : W_e_i[src], 0.f);
        else             w = -fmaxf((co < 32) ? W_i_e[src] : W_i_i[src], 0.f);
        unsigned short h, l;
        bf16split(w, h, l);
        uint32_t base = (uint32_t)t*73728 + (uint32_t)tau*8192 + (uint32_t)co*128;
        uint32_t swz  = (uint32_t)(co & 7) << 4;
        g_Bst[(base + (((uint32_t)ci*2)      ^ swz)) >> 1] = h;   // Whi bytes [0,64)
        g_Bst[(base + ((64u + (uint32_t)ci*2) ^ swz)) >> 1] = l;  // Wlo bytes [64,128)
    } else if (fid < 3*9*64*32 + 9*32*32) {
        int f2  = fid - 3*9*64*32;
        int ci  = f2 & 31;
        int r   = f2 >> 5;
        int co  = r & 31;
        int tau = r >> 5;
        float w = fmaxf(W_e_out[co*288 + ci*9 + tau], 0.f);
        unsigned short h, l;
        bf16split(w, h, l);
        uint32_t base = (uint32_t)tau*4096 + (uint32_t)co*128;
        uint32_t swz  = (uint32_t)(co & 7) << 4;
        g_Bout[(base + (((uint32_t)ci*2)      ^ swz)) >> 1] = h;
        g_Bout[(base + ((64u + (uint32_t)ci*2) ^ swz)) >> 1] = l;
    }
    if (blockIdx.x == 0 && threadIdx.x < 64) {
        int co = threadIdx.x;
        if (co < 32) {
            g_bcomb[co]  = b_in_e[co] + fmaxf(b_e_e[co], 0.f) - fmaxf(b_i_e[co], 0.f);
            g_invtau[co] = 1.f / fmaxf(tau_e[co], 1.f);
            g_bout[co]   = fmaxf(b_e_out[co], 0.f);
        } else {
            int c = co - 32;
            g_bcomb[co]  = b_in_i[c] + fmaxf(b_e_i[c], 0.f) - fmaxf(b_i_i[c], 0.f);
            g_invtau[co] = 1.f / fmaxf(tau_i[c], 1.f);
        }
    }
}

// stage fp32 halo tile -> A rows: [hi 32ci | lo 32ci] bf16, swizzled within 128B row
__device__ __forceinline__ void stage_A(char* sm, int a_off, const float* __restrict__ src,
                                        int ty0, int tx0, int tid)
{
    for (int r = tid; r < NROWS; r += 256) {
        int ry = r / 34, rx = r % 34;
        int gy = ty0 + ry - 1, gx = tx0 + rx - 1;
        bool ok = ((unsigned)gy < 128u) && ((unsigned)gx < 128u);
        const float* p = src + (size_t)gy * Ww + gx;
        uint32_t swz = (uint32_t)(r & 7) << 4;
        char* rowp = sm + a_off + (size_t)r * 128;
        #pragma unroll
        for (int j = 0; j < 4; j++) {
            uint32_t hw[4], lw[4];
            #pragma unroll
            for (int u = 0; u < 4; u++) {
                int ci = 8*j + 2*u;
                float v0 = ok ? p[(size_t)ci * HW]       : 0.f;
                float v1 = ok ? p[(size_t)(ci+1) * HW]   : 0.f;
                unsigned short h0, l0, h1, l1;
                bf16split(v0, h0, l0);
                bf16split(v1, h1, l1);
                hw[u] = (uint32_t)h0 | ((uint32_t)h1 << 16);
                lw[u] = (uint32_t)l0 | ((uint32_t)l1 << 16);
            }
            *(uint4*)(rowp + (((uint32_t)(j*16))       ^ swz)) = make_uint4(hw[0], hw[1], hw[2], hw[3]);
            *(uint4*)(rowp + (((uint32_t)(64 + j*16))  ^ swz)) = make_uint4(lw[0], lw[1], lw[2], lw[3]);
        }
    }
}

// ---------------- state kernel: 6 convs (HMMA) -> tanh -> leaky integrate ----------------
__global__ void __launch_bounds__(256)
state_kernel(const float* __restrict__ x, const float* __restrict__ he,
             const float* __restrict__ hi, float* __restrict__ out)
{
    extern __shared__ char sm[];
    const int tid  = threadIdx.x;
    const int w    = tid >> 5;
    const int lane = tid & 31;
    const int gid  = lane >> 2;      // group id (0..7)
    const int tig  = lane & 3;       // thread in group (0..3)
    const int b    = blockIdx.z;
    const int ty0  = blockIdx.y * 8;
    const int tx0  = blockIdx.x * 32;

    float acc[2][8][4];
    #pragma unroll
    for (int mt = 0; mt < 2; mt++)
        #pragma unroll
        for (int n = 0; n < 8; n++)
            #pragma unroll
            for (int q = 0; q < 4; q++) acc[mt][n][q] = 0.f;

    const float* srcs[3] = {x, he, hi};

    // warp's base A-row (output px m = w*32 + mt*16 + gid; all same py = w)
    const int hrow_base = (w + 1) * 34 + 1 + gid;   // + mt*16 + shift later

    for (int t = 0; t < 3; t++) {
        {
            const uint4* bsrc = (const uint4*)g_Bst + (size_t)t * (ST_B_SZ/16);
            uint4* bdst = (uint4*)(sm + ST_B_OFF);
            for (int i = tid; i < ST_B_SZ/16; i += 256) bdst[i] = bsrc[i];
        }
        stage_A(sm, ST_A_OFF, srcs[t] + (size_t)b * CHW, ty0, tx0, tid);
        __syncthreads();

        #pragma unroll 1
        for (int tap = 0; tap < 9; tap++) {
            const int shift = ((tap/3) - 1) * 34 + (tap % 3) - 1;
            const uint32_t btap = ST_B_OFF + (uint32_t)tap * 8192;
            // A rows for this tap: mt=0: r, r+8 ; mt=1: r+16, r+24
            const int r00 = hrow_base + shift;

            #pragma unroll
            for (int s = 0; s < 6; s++) {
                const int aoff = c_aoffB[s] + 4*tig;
                const int boff = c_boffB[s] + 4*tig;

                uint32_t A0[2], A1[2], A2[2], A3[2];
                #pragma unroll
                for (int mt = 0; mt < 2; mt++) {
                    int ra = r00 + mt*16;
                    int rb = ra + 8;
                    uint32_t sa = (uint32_t)(ra & 7) << 4;
                    uint32_t sb = (uint32_t)(rb & 7) << 4;
                    uint32_t ba = ST_A_OFF + (uint32_t)ra * 128;
                    uint32_t bb = ST_A_OFF + (uint32_t)rb * 128;
                    A0[mt] = lds32(sm, ba + (((uint32_t)aoff)        ^ sa));
                    A1[mt] = lds32(sm, bb + (((uint32_t)aoff)        ^ sb));
                    A2[mt] = lds32(sm, ba + (((uint32_t)(aoff + 16)) ^ sa));
                    A3[mt] = lds32(sm, bb + (((uint32_t)(aoff + 16)) ^ sb));
                }
                uint32_t B0[8], B1[8];
                const uint32_t bswz = (uint32_t)gid << 4;
                #pragma unroll
                for (int n = 0; n < 8; n++) {
                    uint32_t brow = btap + ((uint32_t)(n*8 + gid)) * 128;
                    B0[n] = lds32(sm, brow + (((uint32_t)boff)        ^ bswz));
                    B1[n] = lds32(sm, brow + (((uint32_t)(boff + 16)) ^ bswz));
                }
                #pragma unroll
                for (int mt = 0; mt < 2; mt++)
                    #pragma unroll
                    for (int n = 0; n < 8; n++)
                        mma16816(acc[mt][n], A0[mt], A1[mt], A2[mt], A3[mt], B0[n], B1[n]);
            }
        }
        __syncthreads();
    }

    // epilogue: bias + tanh + leaky integration
    #pragma unroll
    for (int mt = 0; mt < 2; mt++) {
        #pragma unroll
        for (int half = 0; half < 2; half++) {     // rows m0 (gid) and m0+8
            int m  = w*32 + mt*16 + gid + half*8;
            int py = ty0 + (m >> 5);
            int px = tx0 + (m & 31);
            size_t pidx = (size_t)b * CHW + (size_t)py * Ww + px;
            #pragma unroll
            for (int n = 0; n < 8; n++) {
                #pragma unroll
                for (int q = 0; q < 2; q++) {
                    int co  = n*8 + 2*tig + q;
                    float v = acc[mt][n][half*2 + q] + g_bcomb[co];
                    float inv = g_invtau[co];
                    float cnd = fast_tanh(v);
                    if (co < 32) {
                        float h = (inv < 1.f) ? he[pidx + (size_t)co * HW] : 0.f;
                        out[(size_t)NTOT + pidx + (size_t)co * HW] = (1.f - inv)*h + inv*cnd;
                    } else {
                        int c = co - 32;
                        float h = (inv < 1.f) ? hi[pidx + (size_t)c * HW] : 0.f;
                        out[(size_t)2*NTOT + pidx + (size_t)c * HW] = (1.f - inv)*h + inv*cnd;
                    }
                }
            }
        }
    }
}

// ---------------- out kernel: tanh(conv(h_e_new, relu(W_e_out)) + relu(b)) ----------------
__global__ void __launch_bounds__(256)
out_kernel(const float* __restrict__ hen, float* __restrict__ out)
{
    extern __shared__ char sm[];
    const int tid  = threadIdx.x;
    const int w    = tid >> 5;
    const int lane = tid & 31;
    const int gid  = lane >> 2;
    const int tig  = lane & 3;
    const int b    = blockIdx.z;
    const int ty0  = blockIdx.y * 8;
    const int tx0  = blockIdx.x * 32;

    float acc[2][4][4];
    #pragma unroll
    for (int mt = 0; mt < 2; mt++)
        #pragma unroll
        for (int n = 0; n < 4; n++)
            #pragma unroll
            for (int q = 0; q < 4; q++) acc[mt][n][q] = 0.f;

    {
        const uint4* bsrc = (const uint4*)g_Bout;
        uint4* bdst = (uint4*)(sm + OU_B_OFF);
        for (int i = tid; i < OU_B_SZ/16; i += 256) bdst[i] = bsrc[i];
    }
    stage_A(sm, OU_A_OFF, hen + (size_t)b * CHW, ty0, tx0, tid);
    __syncthreads();

    const int hrow_base = (w + 1) * 34 + 1 + gid;

    #pragma unroll 1
    for (int tap = 0; tap < 9; tap++) {
        const int shift = ((tap/3) - 1) * 34 + (tap % 3) - 1;
        const uint32_t btap = OU_B_OFF + (uint32_t)tap * 4096;
        const int r00 = hrow_base + shift;

        #pragma unroll
        for (int s = 0; s < 6; s++) {
            const int aoff = c_aoffB[s] + 4*tig;
            const int boff = c_boffB[s] + 4*tig;

            uint32_t A0[2], A1[2], A2[2], A3[2];
            #pragma unroll
            for (int mt = 0; mt < 2; mt++) {
                int ra = r00 + mt*16;
                int rb = ra + 8;
                uint32_t sa = (uint32_t)(ra & 7) << 4;
                uint32_t sb = (uint32_t)(rb & 7) << 4;
                uint32_t ba = OU_A_OFF + (uint32_t)ra * 128;
                uint32_t bb = OU_A_OFF + (uint32_t)rb * 128;
                A0[mt] = lds32(sm, ba + (((uint32_t)aoff)        ^ sa));
                A1[mt] = lds32(sm, bb + (((uint32_t)aoff)        ^ sb));
                A2[mt] = lds32(sm, ba + (((uint32_t)(aoff + 16)) ^ sa));
                A3[mt] = lds32(sm, bb + (((uint32_t)(aoff + 16)) ^ sb));
            }
            uint32_t B0[4], B1[4];
            const uint32_t bswz = (uint32_t)gid << 4;
            #pragma unroll
            for (int n = 0; n < 4; n++) {
                uint32_t brow = btap + ((uint32_t)(n*8 + gid)) * 128;
                B0[n] = lds32(sm, brow + (((uint32_t)boff)        ^ bswz));
                B1[n] = lds32(sm, brow + (((uint32_t)(boff + 16)) ^ bswz));
            }
            #pragma unroll
            for (int mt = 0; mt < 2; mt++)
                #pragma unroll
                for (int n = 0; n < 4; n++)
                    mma16816(acc[mt][n], A0[mt], A1[mt], A2[mt], A3[mt], B0[n], B1[n]);
        }
    }

    #pragma unroll
    for (int mt = 0; mt < 2; mt++) {
        #pragma unroll
        for (int half = 0; half < 2; half++) {
            int m  = w*32 + mt*16 + gid + half*8;
            int py = ty0 + (m >> 5);
            int px = tx0 + (m & 31);
            size_t pidx = (size_t)b * CHW + (size_t)py * Ww + px;
            #pragma unroll
            for (int n = 0; n < 4; n++) {
                #pragma unroll
                for (int q = 0; q < 2; q++) {
                    int co  = n*8 + 2*tig + q;
                    float v = acc[mt][n][half*2 + q] + g_bout[co];
                    out[pidx + (size_t)co * HW] = fast_tanh(v);
                }
            }
        }
    }
}

extern "C" void kernel_launch(void* const* d_in, const int* in_sizes, int n_in,
                              void* d_out, int out_size)
{
    (void)in_sizes; (void)n_in; (void)out_size;
    const float* x  = (const float*)d_in[0];
    const float* he = (const float*)d_in[1];
    const float* hi = (const float*)d_in[2];
    float* out = (float*)d_out;

    cudaFuncSetAttribute(state_kernel, cudaFuncAttributeMaxDynamicSharedMemorySize, ST_SMEM);
    cudaFuncSetAttribute(out_kernel,   cudaFuncAttributeMaxDynamicSharedMemorySize, OU_SMEM);

    prep_kernel<<<252, 256>>>(
        (const float*)d_in[3],  (const float*)d_in[4],
        (const float*)d_in[5],  (const float*)d_in[6],
        (const float*)d_in[7],  (const float*)d_in[8],
        (const float*)d_in[9],  (const float*)d_in[10],
        (const float*)d_in[11], (const float*)d_in[12],
        (const float*)d_in[13], (const float*)d_in[14],
        (const float*)d_in[15], (const float*)d_in[16],
        (const float*)d_in[17], (const float*)d_in[18]);

    dim3 grid(4, 16, Bn);   // 32-px x 8-row tiles, batch
    state_kernel<<<grid, 256, ST_SMEM>>>(x, he, hi, out);
    out_kernel<<<grid, 256, OU_SMEM>>>(out + NTOT, out);
}

// round 6
// speedup vs baseline: 4.1094x; 1.0913x over previous
#include <cuda_runtime.h>
#include <math.h>
#include <stdint.h>

#define Bn 16
#define Cc 32
#define Hh 128
#define Ww 128
#define HW (Hh*Ww)
#define CHW (Cc*HW)
#define NTOT (Bn*CHW)

// block tile: 8 out rows x 32 out cols = 256 px; halo 10x34 = 340 A rows
#define NROWS 340

#define ST_B_OFF 0
#define ST_B_SZ  73728
#define ST_A_OFF ST_B_SZ
#define A_SZ     (NROWS*128)
#define ST_SMEM  (ST_B_SZ + A_SZ)        // 117,248 B
#define OU_B_OFF 0
#define OU_B_SZ  36864
#define OU_A_OFF OU_B_SZ
#define OU_SMEM  (OU_B_SZ + A_SZ)        // 80,384 B

// global A-row images: [t(4)][b*HW + pix] rows of 128B ([hi 32ci | lo 32ci] bf16)
// t: 0=x, 1=h_e, 2=h_i, 3=h_e_new.  4*16*16384 rows * 8 uint4 = 134 MB
__device__ uint4 g_Arows[(size_t)4*Bn*HW*8];

__device__ __align__(16) unsigned short g_Bst[3*36864];  // pre-swizzled B, 3 x 73728 B
__device__ __align__(16) unsigned short g_Bout[18432];   // pre-swizzled B_out, 36864 B
__device__ float g_bcomb[64];
__device__ float g_bout[32];
__device__ float g_invtau[64];

// ---------------- helpers ----------------
__device__ __forceinline__ uint32_t smem_u32(const void* p) {
    uint32_t a;
    asm("{ .reg .u64 t; cvta.to.shared.u64 t, %1; cvt.u32.u64 %0, t; }" : "=r"(a) : "l"(p));
    return a;
}
__device__ __forceinline__ void bf16split(float v, unsigned short& h, unsigned short& l) {
    asm("cvt.rn.bf16.f32 %0, %1;" : "=h"(h) : "f"(v));
    float hf;
    asm("cvt.f32.bf16 %0, %1;" : "=f"(hf) : "h"(h));
    asm("cvt.rn.bf16.f32 %0, %1;" : "=h"(l) : "f"(v - hf));
}
__device__ __forceinline__ float fast_tanh(float x) {
    float e, r;
    asm("ex2.approx.f32 %0, %1;" : "=f"(e) : "f"(x * 2.8853900817779268f)); // e^{2x}
    asm("rcp.approx.f32 %0, %1;" : "=f"(r) : "f"(e + 1.f));
    return fmaf(-2.f, r, 1.f);
}
__device__ __forceinline__ void mma16816(float* c,
    uint32_t a0, uint32_t a1, uint32_t a2, uint32_t a3, uint32_t b0, uint32_t b1)
{
    asm volatile(
        "mma.sync.aligned.m16n8k16.row.col.f32.bf16.bf16.f32 "
        "{%0,%1,%2,%3}, {%4,%5,%6,%7}, {%8,%9}, {%0,%1,%2,%3};"
        : "+f"(c[0]), "+f"(c[1]), "+f"(c[2]), "+f"(c[3])
        : "r"(a0), "r"(a1), "r"(a2), "r"(a3), "r"(b0), "r"(b1));
}
__device__ __forceinline__ uint32_t lds32(const char* sm, uint32_t off) {
    return *(const uint32_t*)(sm + off);
}
__device__ __forceinline__ void cp16(uint32_t smdst, const void* gsrc) {
    asm volatile("cp.async.cg.shared.global [%0], [%1], 16;" :: "r"(smdst), "l"(gsrc));
}
#define CP_COMMIT() asm volatile("cp.async.commit_group;" ::: "memory")
#define CP_WAIT0()  asm volatile("cp.async.wait_group 0;" ::: "memory")

// split-precision pass schedule (byte offsets into 128B rows)
__device__ __constant__ int c_aoffB[6] = {0, 32, 64, 96, 0, 32};
__device__ __constant__ int c_boffB[6] = {0, 32, 0, 32, 64, 96};

// ---------------- prep: fold Dale rectify/sign, bf16 hi/lo split, pre-swizzle ----------------
__global__ void prep_kernel(
    const float* __restrict__ W_in_e, const float* __restrict__ b_in_e,
    const float* __restrict__ W_in_i, const float* __restrict__ b_in_i,
    const float* __restrict__ W_e_e,  const float* __restrict__ b_e_e,
    const float* __restrict__ W_e_i,  const float* __restrict__ b_e_i,
    const float* __restrict__ W_e_out,const float* __restrict__ b_e_out,
    const float* __restrict__ W_i_e,  const float* __restrict__ b_i_e,
    const float* __restrict__ W_i_i,  const float* __restrict__ b_i_i,
    const float* __restrict__ tau_e,  const float* __restrict__ tau_i)
{
    int fid = blockIdx.x * 256 + threadIdx.x;
    if (fid < 3*9*64*32) {
        int ci  = fid & 31;
        int r   = fid >> 5;
        int co  = r & 63;  r >>= 6;
        int tau = r % 9;
        int t   = r / 9;
        int src = (co & 31) * 288 + ci * 9 + tau;   // OIHW
        float w;
        if (t == 0)      w = (co < 32) ? W_in_e[src] : W_in_i[src];
        else if (t == 1) w = fmaxf((co < 32) ? W_e_e[src] : W_e_i[src], 0.f);
        else             w = -fmaxf((co < 32) ? W_i_e[src] : W_i_i[src], 0.f);
        unsigned short h, l;
        bf16split(w, h, l);
        uint32_t base = (uint32_t)t*73728 + (uint32_t)tau*8192 + (uint32_t)co*128;
        uint32_t swz  = (uint32_t)(co & 7) << 4;
        g_Bst[(base + (((uint32_t)ci*2)       ^ swz)) >> 1] = h;
        g_Bst[(base + ((64u + (uint32_t)ci*2) ^ swz)) >> 1] = l;
    } else if (fid < 3*9*64*32 + 9*32*32) {
        int f2  = fid - 3*9*64*32;
        int ci  = f2 & 31;
        int r   = f2 >> 5;
        int co  = r & 31;
        int tau = r >> 5;
        float w = fmaxf(W_e_out[co*288 + ci*9 + tau], 0.f);
        unsigned short h, l;
        bf16split(w, h, l);
        uint32_t base = (uint32_t)tau*4096 + (uint32_t)co*128;
        uint32_t swz  = (uint32_t)(co & 7) << 4;
        g_Bout[(base + (((uint32_t)ci*2)       ^ swz)) >> 1] = h;
        g_Bout[(base + ((64u + (uint32_t)ci*2) ^ swz)) >> 1] = l;
    }
    if (blockIdx.x == 0 && threadIdx.x < 64) {
        int co = threadIdx.x;
        if (co < 32) {
            g_bcomb[co]  = b_in_e[co] + fmaxf(b_e_e[co], 0.f) - fmaxf(b_i_e[co], 0.f);
            g_invtau[co] = 1.f / fmaxf(tau_e[co], 1.f);
            g_bout[co]   = fmaxf(b_e_out[co], 0.f);
        } else {
            int c = co - 32;
            g_bcomb[co]  = b_in_i[c] + fmaxf(b_e_i[c], 0.f) - fmaxf(b_i_i[c], 0.f);
            g_invtau[co] = 1.f / fmaxf(tau_i[c], 1.f);
        }
    }
}

// ---------------- convert: NCHW fp32 -> per-pixel 128B bf16 hi/lo rows ----------------
__global__ void __launch_bounds__(256)
convert_kernel(const float* __restrict__ x, const float* __restrict__ he,
               const float* __restrict__ hi)
{
    int gidx = blockIdx.x * 256 + threadIdx.x;     // 0 .. 3*Bn*HW-1
    int t = gidx / (Bn*HW);
    int p = gidx - t * (Bn*HW);
    int b = p / HW;
    int pix = p - b * HW;
    const float* src = (t == 0 ? x : (t == 1 ? he : hi)) + (size_t)b * CHW + pix;
    uint4* dst = g_Arows + ((size_t)t * (Bn*HW) + p) * 8;

    uint32_t hw[16], lw[16];
    #pragma unroll
    for (int k = 0; k < 16; k++) {
        float v0 = src[(size_t)(2*k)   * HW];
        float v1 = src[(size_t)(2*k+1) * HW];
        unsigned short h0, l0, h1, l1;
        bf16split(v0, h0, l0);
        bf16split(v1, h1, l1);
        hw[k] = (uint32_t)h0 | ((uint32_t)h1 << 16);
        lw[k] = (uint32_t)l0 | ((uint32_t)l1 << 16);
    }
    #pragma unroll
    for (int j = 0; j < 4; j++) {
        dst[j]     = make_uint4(hw[4*j], hw[4*j+1], hw[4*j+2], hw[4*j+3]);
        dst[4 + j] = make_uint4(lw[4*j], lw[4*j+1], lw[4*j+2], lw[4*j+3]);
    }
}

// stage: pure cp.async copies, swizzle applied on SMEM address
__device__ __forceinline__ void stage_A_copy(uint32_t smA, int t, int b,
                                             int ty0, int tx0, int tid)
{
    const char* gbase = (const char*)(g_Arows + (size_t)t * (Bn*HW) * 8)
                      + (size_t)b * HW * 128;
    for (int i = tid; i < NROWS*8; i += 256) {
        int r = i >> 3, c = i & 7;
        int ry = r / 34, rx = r - ry*34;
        int gy = ty0 + ry - 1, gx = tx0 + rx - 1;
        uint32_t dst = smA + (uint32_t)r*128 + (((uint32_t)c*16) ^ ((uint32_t)(r & 7) << 4));
        if (((unsigned)gy < 128u) && ((unsigned)gx < 128u)) {
            cp16(dst, gbase + ((size_t)(gy*128 + gx))*128 + c*16);
        } else {
            *(uint4*)(uintptr_t)0 ; // never taken placeholder (removed below)
        }
    }
}

// ---------------- state kernel ----------------
__global__ void __launch_bounds__(256)
state_kernel(const float* __restrict__ he, const float* __restrict__ hi,
             float* __restrict__ out)
{
    extern __shared__ char sm[];
    const uint32_t smb = smem_u32(sm);
    const int tid  = threadIdx.x;
    const int w    = tid >> 5;
    const int lane = tid & 31;
    const int gid  = lane >> 2;
    const int tig  = lane & 3;
    const int b    = blockIdx.z;
    const int ty0  = blockIdx.y * 8;
    const int tx0  = blockIdx.x * 32;

    float acc[2][8][4];
    #pragma unroll
    for (int mt = 0; mt < 2; mt++)
        #pragma unroll
        for (int n = 0; n < 8; n++)
            #pragma unroll
            for (int q = 0; q < 4; q++) acc[mt][n][q] = 0.f;

    const int hrow_base = (w + 1) * 34 + 1 + gid;

    for (int t = 0; t < 3; t++) {
        // B tile copy (cp.async)
        {
            const char* bsrc = (const char*)g_Bst + (size_t)t * ST_B_SZ;
            for (int i = tid; i < ST_B_SZ/16; i += 256)
                cp16(smb + ST_B_OFF + (uint32_t)i*16, bsrc + (size_t)i*16);
        }
        // A tile copy (cp.async, zero halo)
        {
            const char* gbase = (const char*)g_Arows
                              + ((size_t)t * (Bn*HW) + (size_t)b * HW) * 128;
            for (int i = tid; i < NROWS*8; i += 256) {
                int r = i >> 3, c = i & 7;
                int ry = r / 34, rx = r - ry*34;
                int gy = ty0 + ry - 1, gx = tx0 + rx - 1;
                uint32_t dst = smb + ST_A_OFF + (uint32_t)r*128
                             + (((uint32_t)c*16) ^ ((uint32_t)(r & 7) << 4));
                if (((unsigned)gy < 128u) && ((unsigned)gx < 128u))
                    cp16(dst, gbase + ((size_t)(gy*128 + gx))*128 + c*16);
                else
                    *(uint4*)(sm + (dst - smb)) = make_uint4(0,0,0,0);
            }
        }
        CP_COMMIT();
        CP_WAIT0();
        __syncthreads();

        #pragma unroll 1
        for (int tap = 0; tap < 9; tap++) {
            const int shift = ((tap/3) - 1) * 34 + (tap % 3) - 1;
            const uint32_t btap = ST_B_OFF + (uint32_t)tap * 8192;
            const int r00 = hrow_base + shift;

            #pragma unroll
            for (int s = 0; s < 6; s++) {
                const int aoff = c_aoffB[s] + 4*tig;
                const int boff = c_boffB[s] + 4*tig;

                uint32_t A0[2], A1[2], A2[2], A3[2];
                #pragma unroll
                for (int mt = 0; mt < 2; mt++) {
                    int ra = r00 + mt*16;
                    int rb = ra + 8;
                    uint32_t sa = (uint32_t)(ra & 7) << 4;
                    uint32_t sb = (uint32_t)(rb & 7) << 4;
                    uint32_t ba = ST_A_OFF + (uint32_t)ra * 128;
                    uint32_t bb = ST_A_OFF + (uint32_t)rb * 128;
                    A0[mt] = lds32(sm, ba + (((uint32_t)aoff)        ^ sa));
                    A1[mt] = lds32(sm, bb + (((uint32_t)aoff)        ^ sb));
                    A2[mt] = lds32(sm, ba + (((uint32_t)(aoff + 16)) ^ sa));
                    A3[mt] = lds32(sm, bb + (((uint32_t)(aoff + 16)) ^ sb));
                }
                uint32_t B0[8], B1[8];
                const uint32_t bswz = (uint32_t)gid << 4;
                #pragma unroll
                for (int n = 0; n < 8; n++) {
                    uint32_t brow = btap + ((uint32_t)(n*8 + gid)) * 128;
                    B0[n] = lds32(sm, brow + (((uint32_t)boff)        ^ bswz));
                    B1[n] = lds32(sm, brow + (((uint32_t)(boff + 16)) ^ bswz));
                }
                #pragma unroll
                for (int mt = 0; mt < 2; mt++)
                    #pragma unroll
                    for (int n = 0; n < 8; n++)
                        mma16816(acc[mt][n], A0[mt], A1[mt], A2[mt], A3[mt], B0[n], B1[n]);
            }
        }
        __syncthreads();
    }

    // epilogue: bias + tanh + leaky integrate; also emit h_e_new rows (t=3)
    uint32_t* rowbase = (uint32_t*)(g_Arows + (size_t)3 * (Bn*HW) * 8);
    #pragma unroll
    for (int mt = 0; mt < 2; mt++) {
        #pragma unroll
        for (int half = 0; half < 2; half++) {
            int m  = w*32 + mt*16 + gid + half*8;
            int py = ty0 + (m >> 5);
            int px = tx0 + (m & 31);
            size_t pidx = (size_t)b * CHW + (size_t)py * Ww + px;
            uint32_t* rp = rowbase + ((size_t)b * HW + (size_t)py * Ww + px) * 32;
            #pragma unroll
            for (int n = 0; n < 8; n++) {
                float v0, v1;
                {
                    int co = n*8 + 2*tig;
                    float a0 = acc[mt][n][half*2]     + g_bcomb[co];
                    float a1 = acc[mt][n][half*2 + 1] + g_bcomb[co+1];
                    float i0 = g_invtau[co], i1 = g_invtau[co+1];
                    float c0 = fast_tanh(a0), c1 = fast_tanh(a1);
                    if (co < 32) {
                        float h0 = (i0 < 1.f) ? he[pidx + (size_t)co * HW]     : 0.f;
                        float h1 = (i1 < 1.f) ? he[pidx + (size_t)(co+1) * HW] : 0.f;
                        v0 = (1.f - i0)*h0 + i0*c0;
                        v1 = (1.f - i1)*h1 + i1*c1;
                        out[(size_t)NTOT + pidx + (size_t)co * HW]     = v0;
                        out[(size_t)NTOT + pidx + (size_t)(co+1) * HW] = v1;
                        // h_e_new row-format write
                        unsigned short h0b, l0b, h1b, l1b;
                        bf16split(v0, h0b, l0b);
                        bf16split(v1, h1b, l1b);
                        int widx = co >> 1;                     // pair index
                        rp[widx]      = (uint32_t)h0b | ((uint32_t)h1b << 16);
                        rp[16 + widx] = (uint32_t)l0b | ((uint32_t)l1b << 16);
                    } else {
                        int c = co - 32;
                        float h0 = (i0 < 1.f) ? hi[pidx + (size_t)c * HW]     : 0.f;
                        float h1 = (i1 < 1.f) ? hi[pidx + (size_t)(c+1) * HW] : 0.f;
                        v0 = (1.f - i0)*h0 + i0*c0;
                        v1 = (1.f - i1)*h1 + i1*c1;
                        out[(size_t)2*NTOT + pidx + (size_t)c * HW]     = v0;
                        out[(size_t)2*NTOT + pidx + (size_t)(c+1) * HW] = v1;
                    }
                }
            }
        }
    }
}

// ---------------- out kernel ----------------
__global__ void __launch_bounds__(256)
out_kernel(float* __restrict__ out)
{
    extern __shared__ char sm[];
    const uint32_t smb = smem_u32(sm);
    const int tid  = threadIdx.x;
    const int w    = tid >> 5;
    const int lane = tid & 31;
    const int gid  = lane >> 2;
    const int tig  = lane & 3;
    const int b    = blockIdx.z;
    const int ty0  = blockIdx.y * 8;
    const int tx0  = blockIdx.x * 32;

    float acc[2][4][4];
    #pragma unroll
    for (int mt = 0; mt < 2; mt++)
        #pragma unroll
        for (int n = 0; n < 4; n++)
            #pragma unroll
            for (int q = 0; q < 4; q++) acc[mt][n][q] = 0.f;

    {
        const char* bsrc = (const char*)g_Bout;
        for (int i = tid; i < OU_B_SZ/16; i += 256)
            cp16(smb + OU_B_OFF + (uint32_t)i*16, bsrc + (size_t)i*16);
    }
    {
        const char* gbase = (const char*)g_Arows
                          + ((size_t)3 * (Bn*HW) + (size_t)b * HW) * 128;
        for (int i = tid; i < NROWS*8; i += 256) {
            int r = i >> 3, c = i & 7;
            int ry = r / 34, rx = r - ry*34;
            int gy = ty0 + ry - 1, gx = tx0 + rx - 1;
            uint32_t dst = smb + OU_A_OFF + (uint32_t)r*128
                         + (((uint32_t)c*16) ^ ((uint32_t)(r & 7) << 4));
            if (((unsigned)gy < 128u) && ((unsigned)gx < 128u))
                cp16(dst, gbase + ((size_t)(gy*128 + gx))*128 + c*16);
            else
                *(uint4*)(sm + (dst - smb)) = make_uint4(0,0,0,0);
        }
    }
    CP_COMMIT();
    CP_WAIT0();
    __syncthreads();

    const int hrow_base = (w + 1) * 34 + 1 + gid;

    #pragma unroll 1
    for (int tap = 0; tap < 9; tap++) {
        const int shift = ((tap/3) - 1) * 34 + (tap % 3) - 1;
        const uint32_t btap = OU_B_OFF + (uint32_t)tap * 4096;
        const int r00 = hrow_base + shift;

        #pragma unroll
        for (int s = 0; s < 6; s++) {
            const int aoff = c_aoffB[s] + 4*tig;
            const int boff = c_boffB[s] + 4*tig;

            uint32_t A0[2], A1[2], A2[2], A3[2];
            #pragma unroll
            for (int mt = 0; mt < 2; mt++) {
                int ra = r00 + mt*16;
                int rb = ra + 8;
                uint32_t sa = (uint32_t)(ra & 7) << 4;
                uint32_t sb = (uint32_t)(rb & 7) << 4;
                uint32_t ba = OU_A_OFF + (uint32_t)ra * 128;
                uint32_t bb = OU_A_OFF + (uint32_t)rb * 128;
                A0[mt] = lds32(sm, ba + (((uint32_t)aoff)        ^ sa));
                A1[mt] = lds32(sm, bb + (((uint32_t)aoff)        ^ sb));
                A2[mt] = lds32(sm, ba + (((uint32_t)(aoff + 16)) ^ sa));
                A3[mt] = lds32(sm, bb + (((uint32_t)(aoff + 16)) ^ sb));
            }
            uint32_t B0[4], B1[4];
            const uint32_t bswz = (uint32_t)gid << 4;
            #pragma unroll
            for (int n = 0; n < 4; n++) {
                uint32_t brow = btap + ((uint32_t)(n*8 + gid)) * 128;
                B0[n] = lds32(sm, brow + (((uint32_t)boff)        ^ bswz));
                B1[n] = lds32(sm, brow + (((uint32_t)(boff + 16)) ^ bswz));
            }
            #pragma unroll
            for (int mt = 0; mt < 2; mt++)
                #pragma unroll
                for (int n = 0; n < 4; n++)
                    mma16816(acc[mt][n], A0[mt], A1[mt], A2[mt], A3[mt], B0[n], B1[n]);
        }
    }

    #pragma unroll
    for (int mt = 0; mt < 2; mt++) {
        #pragma unroll
        for (int half = 0; half < 2; half++) {
            int m  = w*32 + mt*16 + gid + half*8;
            int py = ty0 + (m >> 5);
            int px = tx0 + (m & 31);
            size_t pidx = (size_t)b * CHW + (size_t)py * Ww + px;
            #pragma unroll
            for (int n = 0; n < 4; n++) {
                #pragma unroll
                for (int q = 0; q < 2; q++) {
                    int co  = n*8 + 2*tig + q;
                    float v = acc[mt][n][half*2 + q] + g_bout[co];
                    out[pidx + (size_t)co * HW] = fast_tanh(v);
                }
            }
        }
    }
}

extern "C" void kernel_launch(void* const* d_in, const int* in_sizes, int n_in,
                              void* d_out, int out_size)
{
    (void)in_sizes; (void)n_in; (void)out_size;
    const float* x  = (const float*)d_in[0];
    const float* he = (const float*)d_in[1];
    const float* hi = (const float*)d_in[2];
    float* out = (float*)d_out;

    cudaFuncSetAttribute(state_kernel, cudaFuncAttributeMaxDynamicSharedMemorySize, ST_SMEM);
    cudaFuncSetAttribute(out_kernel,   cudaFuncAttributeMaxDynamicSharedMemorySize, OU_SMEM);

    prep_kernel<<<252, 256>>>(
        (const float*)d_in[3],  (const float*)d_in[4],
        (const float*)d_in[5],  (const float*)d_in[6],
        (const float*)d_in[7],  (const float*)d_in[8],
        (const float*)d_in[9],  (const float*)d_in[10],
        (const float*)d_in[11], (const float*)d_in[12],
        (const float*)d_in[13], (const float*)d_in[14],
        (const float*)d_in[15], (const float*)d_in[16],
        (const float*)d_in[17], (const float*)d_in[18]);

    convert_kernel<<<(3*Bn*HW)/256, 256>>>(x, he, hi);

    dim3 grid(4, 16, Bn);
    state_kernel<<<grid, 256, ST_SMEM>>>(he, hi, out);
    out_kernel<<<grid, 256, OU_SMEM>>>(out);
}

// round 7
// speedup vs baseline: 4.2117x; 1.0249x over previous
#include <cuda_runtime.h>
#include <math.h>
#include <stdint.h>

#define Bn 16
#define Cc 32
#define Hh 128
#define Ww 128
#define HW (Hh*Ww)
#define CHW (Cc*HW)
#define NTOT (Bn*CHW)

// block tile: 16 out rows x 32 out cols = 512 px; halo 18x34 = 612 A rows
#define THREADS 512
#define NROWS 612

#define ST_B_OFF 0
#define ST_B_SZ  73728
#define ST_A_OFF ST_B_SZ
#define A_SZ     (NROWS*128)             // 78336
#define ST_SMEM  (ST_B_SZ + A_SZ)        // 152,064 B
#define OU_B_OFF 0
#define OU_B_SZ  36864
#define OU_A_OFF OU_B_SZ
#define OU_SMEM  (OU_B_SZ + A_SZ)        // 115,200 B

// global A-row images: [t(4)][b*HW + pix] rows of 128B ([hi 32ci | lo 32ci] bf16)
__device__ uint4 g_Arows[(size_t)4*Bn*HW*8];

__device__ __align__(16) unsigned short g_Bst[3*36864];  // pre-swizzled B, 3 x 73728 B
__device__ __align__(16) unsigned short g_Bout[18432];   // pre-swizzled B_out
__device__ float g_bcomb[64];
__device__ float g_bout[32];
__device__ float g_invtau[64];

// ---------------- helpers ----------------
__device__ __forceinline__ uint32_t smem_u32(const void* p) {
    uint32_t a;
    asm("{ .reg .u64 t; cvta.to.shared.u64 t, %1; cvt.u32.u64 %0, t; }" : "=r"(a) : "l"(p));
    return a;
}
__device__ __forceinline__ void bf16split(float v, unsigned short& h, unsigned short& l) {
    asm("cvt.rn.bf16.f32 %0, %1;" : "=h"(h) : "f"(v));
    float hf;
    asm("cvt.f32.bf16 %0, %1;" : "=f"(hf) : "h"(h));
    asm("cvt.rn.bf16.f32 %0, %1;" : "=h"(l) : "f"(v - hf));
}
__device__ __forceinline__ float fast_tanh(float x) {
    float e, r;
    asm("ex2.approx.f32 %0, %1;" : "=f"(e) : "f"(x * 2.8853900817779268f));
    asm("rcp.approx.f32 %0, %1;" : "=f"(r) : "f"(e + 1.f));
    return fmaf(-2.f, r, 1.f);
}
__device__ __forceinline__ void mma16816(float* c,
    uint32_t a0, uint32_t a1, uint32_t a2, uint32_t a3, uint32_t b0, uint32_t b1)
{
    asm volatile(
        "mma.sync.aligned.m16n8k16.row.col.f32.bf16.bf16.f32 "
        "{%0,%1,%2,%3}, {%4,%5,%6,%7}, {%8,%9}, {%0,%1,%2,%3};"
        : "+f"(c[0]), "+f"(c[1]), "+f"(c[2]), "+f"(c[3])
        : "r"(a0), "r"(a1), "r"(a2), "r"(a3), "r"(b0), "r"(b1));
}
__device__ __forceinline__ void ldsm4(uint32_t* r, uint32_t addr) {
    asm volatile("ldmatrix.sync.aligned.m8n8.x4.shared.b16 {%0,%1,%2,%3}, [%4];"
        : "=r"(r[0]), "=r"(r[1]), "=r"(r[2]), "=r"(r[3]) : "r"(addr));
}
__device__ __forceinline__ void cp16(uint32_t smdst, const void* gsrc) {
    asm volatile("cp.async.cg.shared.global [%0], [%1], 16;" :: "r"(smdst), "l"(gsrc));
}
#define CP_COMMIT() asm volatile("cp.async.commit_group;" ::: "memory")
#define CP_WAIT0()  asm volatile("cp.async.wait_group 0;" ::: "memory")

// ---------------- prep ----------------
__global__ void prep_kernel(
    const float* __restrict__ W_in_e, const float* __restrict__ b_in_e,
    const float* __restrict__ W_in_i, const float* __restrict__ b_in_i,
    const float* __restrict__ W_e_e,  const float* __restrict__ b_e_e,
    const float* __restrict__ W_e_i,  const float* __restrict__ b_e_i,
    const float* __restrict__ W_e_out,const float* __restrict__ b_e_out,
    const float* __restrict__ W_i_e,  const float* __restrict__ b_i_e,
    const float* __restrict__ W_i_i,  const float* __restrict__ b_i_i,
    const float* __restrict__ tau_e,  const float* __restrict__ tau_i)
{
    int fid = blockIdx.x * 256 + threadIdx.x;
    if (fid < 3*9*64*32) {
        int ci  = fid & 31;
        int r   = fid >> 5;
        int co  = r & 63;  r >>= 6;
        int tau = r % 9;
        int t   = r / 9;
        int src = (co & 31) * 288 + ci * 9 + tau;   // OIHW
        float w;
        if (t == 0)      w = (co < 32) ? W_in_e[src] : W_in_i[src];
        else if (t == 1) w = fmaxf((co < 32) ? W_e_e[src] : W_e_i[src], 0.f);
        else             w = -fmaxf((co < 32) ? W_i_e[src] : W_i_i[src], 0.f);
        unsigned short h, l;
        bf16split(w, h, l);
        uint32_t base = (uint32_t)t*73728 + (uint32_t)tau*8192 + (uint32_t)co*128;
        uint32_t swz  = (uint32_t)(co & 7) << 4;
        g_Bst[(base + (((uint32_t)ci*2)       ^ swz)) >> 1] = h;
        g_Bst[(base + ((64u + (uint32_t)ci*2) ^ swz)) >> 1] = l;
    } else if (fid < 3*9*64*32 + 9*32*32) {
        int f2  = fid - 3*9*64*32;
        int ci  = f2 & 31;
        int r   = f2 >> 5;
        int co  = r & 31;
        int tau = r >> 5;
        float w = fmaxf(W_e_out[co*288 + ci*9 + tau], 0.f);
        unsigned short h, l;
        bf16split(w, h, l);
        uint32_t base = (uint32_t)tau*4096 + (uint32_t)co*128;
        uint32_t swz  = (uint32_t)(co & 7) << 4;
        g_Bout[(base + (((uint32_t)ci*2)       ^ swz)) >> 1] = h;
        g_Bout[(base + ((64u + (uint32_t)ci*2) ^ swz)) >> 1] = l;
    }
    if (blockIdx.x == 0 && threadIdx.x < 64) {
        int co = threadIdx.x;
        if (co < 32) {
            g_bcomb[co]  = b_in_e[co] + fmaxf(b_e_e[co], 0.f) - fmaxf(b_i_e[co], 0.f);
            g_invtau[co] = 1.f / fmaxf(tau_e[co], 1.f);
            g_bout[co]   = fmaxf(b_e_out[co], 0.f);
        } else {
            int c = co - 32;
            g_bcomb[co]  = b_in_i[c] + fmaxf(b_e_i[c], 0.f) - fmaxf(b_i_i[c], 0.f);
            g_invtau[co] = 1.f / fmaxf(tau_i[c], 1.f);
        }
    }
}

// ---------------- convert: NCHW fp32 -> per-pixel 128B bf16 hi/lo rows ----------------
__global__ void __launch_bounds__(256)
convert_kernel(const float* __restrict__ x, const float* __restrict__ he,
               const float* __restrict__ hi)
{
    int gidx = blockIdx.x * 256 + threadIdx.x;
    int t = gidx / (Bn*HW);
    int p = gidx - t * (Bn*HW);
    int b = p / HW;
    int pix = p - b * HW;
    const float* src = (t == 0 ? x : (t == 1 ? he : hi)) + (size_t)b * CHW + pix;
    uint4* dst = g_Arows + ((size_t)t * (Bn*HW) + p) * 8;

    uint32_t hw[16], lw[16];
    #pragma unroll
    for (int k = 0; k < 16; k++) {
        float v0 = src[(size_t)(2*k)   * HW];
        float v1 = src[(size_t)(2*k+1) * HW];
        unsigned short h0, l0, h1, l1;
        bf16split(v0, h0, l0);
        bf16split(v1, h1, l1);
        hw[k] = (uint32_t)h0 | ((uint32_t)h1 << 16);
        lw[k] = (uint32_t)l0 | ((uint32_t)l1 << 16);
    }
    #pragma unroll
    for (int j = 0; j < 4; j++) {
        dst[j]     = make_uint4(hw[4*j], hw[4*j+1], hw[4*j+2], hw[4*j+3]);
        dst[4 + j] = make_uint4(lw[4*j], lw[4*j+1], lw[4*j+2], lw[4*j+3]);
    }
}

// A tile copy (cp.async, zero halo), 16-row tile
__device__ __forceinline__ void stage_A(char* sm, uint32_t smb, uint32_t a_off,
                                        int t, int b, int ty0, int tx0, int tid)
{
    const char* gbase = (const char*)g_Arows + ((size_t)t * (Bn*HW) + (size_t)b * HW) * 128;
    for (int i = tid; i < NROWS*8; i += THREADS) {
        int r = i >> 3, c = i & 7;
        int ry = r / 34, rx = r - ry*34;
        int gy = ty0 + ry - 1, gx = tx0 + rx - 1;
        uint32_t dst = smb + a_off + (uint32_t)r*128
                     + (((uint32_t)c*16) ^ ((uint32_t)(r & 7) << 4));
        if (((unsigned)gy < 128u) && ((unsigned)gx < 128u))
            cp16(dst, gbase + ((size_t)(gy*128 + gx))*128 + c*16);
        else
            *(uint4*)(sm + (dst - smb)) = make_uint4(0,0,0,0);
    }
}

// ---------------- state kernel ----------------
__global__ void __launch_bounds__(THREADS)
state_kernel(const float* __restrict__ he, const float* __restrict__ hi,
             float* __restrict__ out)
{
    extern __shared__ char sm[];
    const uint32_t smb = smem_u32(sm);
    const int tid  = threadIdx.x;
    const int w    = tid >> 5;
    const int lane = tid & 31;
    const int gid  = lane >> 2;
    const int tig  = lane & 3;
    const int b    = blockIdx.z;
    const int ty0  = blockIdx.y * 16;
    const int tx0  = blockIdx.x * 32;

    float acc[2][8][4];
    #pragma unroll
    for (int mt = 0; mt < 2; mt++)
        #pragma unroll
        for (int n = 0; n < 8; n++)
            #pragma unroll
            for (int q = 0; q < 4; q++) acc[mt][n][q] = 0.f;

    // ldmatrix lane geometry (tap-invariant pieces)
    const int lrow = lane & 15;                 // A row within 16-row fragment
    const uint32_t lcolA = (uint32_t)((lane >> 4) << 4);
    const int hbase = (w + 1) * 34 + 1;         // warp's first output pixel halo row
    // B lane geometry: co within tap-block, and swizzled byte offset per boff
    const uint32_t coB = (uint32_t)(((lane >> 4) & 1) * 8 + (lane & 7));
    const uint32_t bswz = (uint32_t)(lane & 7) << 4;
    uint32_t byteB[4];
    #pragma unroll
    for (int s = 0; s < 4; s++)
        byteB[s] = (uint32_t)((s*32 + (((lane >> 3) & 1) << 4))) ^ bswz;

    for (int t = 0; t < 3; t++) {
        {
            const char* bsrc = (const char*)g_Bst + (size_t)t * ST_B_SZ;
            for (int i = tid; i < ST_B_SZ/16; i += THREADS)
                cp16(smb + ST_B_OFF + (uint32_t)i*16, bsrc + (size_t)i*16);
        }
        stage_A(sm, smb, ST_A_OFF, t, b, ty0, tx0, tid);
        CP_COMMIT();
        CP_WAIT0();
        __syncthreads();

        #pragma unroll 1
        for (int tap = 0; tap < 9; tap++) {
            const int shift = ((tap/3) - 1) * 34 + (tap % 3) - 1;
            const uint32_t btap = smb + ST_B_OFF + (uint32_t)tap * 8192;

            // A lane addresses per mt (row + swizzle key change per tap)
            uint32_t abase[2], aswz[2];
            #pragma unroll
            for (int mt = 0; mt < 2; mt++) {
                int row = hbase + shift + mt*16 + lrow;
                abase[mt] = smb + ST_A_OFF + (uint32_t)row * 128;
                aswz[mt]  = (uint32_t)(row & 7) << 4;
            }
            // cached hi A-sets (aoff 0, 32) and temp for lo sets
            uint32_t Ah0[2][4], Ah1[2][4], At[2][4];
            #pragma unroll
            for (int mt = 0; mt < 2; mt++) {
                ldsm4(Ah0[mt], abase[mt] + ((0u  + lcolA) ^ aswz[mt]));
                ldsm4(Ah1[mt], abase[mt] + ((32u + lcolA) ^ aswz[mt]));
            }

            uint32_t bf[16];
            // ---- B@0 (Whi k0-15): hi*Whi step0, then lo*Whi step0 ----
            #pragma unroll
            for (int p = 0; p < 4; p++)
                ldsm4(bf + 4*p, btap + (coB + (uint32_t)p*16) * 128 + byteB[0]);
            #pragma unroll
            for (int mt = 0; mt < 2; mt++)
                #pragma unroll
                for (int n = 0; n < 8; n++)
                    mma16816(acc[mt][n], Ah0[mt][0],Ah0[mt][1],Ah0[mt][2],Ah0[mt][3],
                             bf[(n>>1)*4 + (n&1)*2], bf[(n>>1)*4 + (n&1)*2 + 1]);
            #pragma unroll
            for (int mt = 0; mt < 2; mt++)
                ldsm4(At[mt], abase[mt] + ((64u + lcolA) ^ aswz[mt]));
            #pragma unroll
            for (int mt = 0; mt < 2; mt++)
                #pragma unroll
                for (int n = 0; n < 8; n++)
                    mma16816(acc[mt][n], At[mt][0],At[mt][1],At[mt][2],At[mt][3],
                             bf[(n>>1)*4 + (n&1)*2], bf[(n>>1)*4 + (n&1)*2 + 1]);
            // ---- B@32 (Whi k16-31): hi step1, lo step1 ----
            #pragma unroll
            for (int p = 0; p < 4; p++)
                ldsm4(bf + 4*p, btap + (coB + (uint32_t)p*16) * 128 + byteB[1]);
            #pragma unroll
            for (int mt = 0; mt < 2; mt++)
                #pragma unroll
                for (int n = 0; n < 8; n++)
                    mma16816(acc[mt][n], Ah1[mt][0],Ah1[mt][1],Ah1[mt][2],Ah1[mt][3],
                             bf[(n>>1)*4 + (n&1)*2], bf[(n>>1)*4 + (n&1)*2 + 1]);
            #pragma unroll
            for (int mt = 0; mt < 2; mt++)
                ldsm4(At[mt], abase[mt] + ((96u + lcolA) ^ aswz[mt]));
            #pragma unroll
            for (int mt = 0; mt < 2; mt++)
                #pragma unroll
                for (int n = 0; n < 8; n++)
                    mma16816(acc[mt][n], At[mt][0],At[mt][1],At[mt][2],At[mt][3],
                             bf[(n>>1)*4 + (n&1)*2], bf[(n>>1)*4 + (n&1)*2 + 1]);
            // ---- B@64 (Wlo k0-15): hi*Wlo step0 ----
            #pragma unroll
            for (int p = 0; p < 4; p++)
                ldsm4(bf + 4*p, btap + (coB + (uint32_t)p*16) * 128 + byteB[2]);
            #pragma unroll
            for (int mt = 0; mt < 2; mt++)
                #pragma unroll
                for (int n = 0; n < 8; n++)
                    mma16816(acc[mt][n], Ah0[mt][0],Ah0[mt][1],Ah0[mt][2],Ah0[mt][3],
                             bf[(n>>1)*4 + (n&1)*2], bf[(n>>1)*4 + (n&1)*2 + 1]);
            // ---- B@96 (Wlo k16-31): hi*Wlo step1 ----
            #pragma unroll
            for (int p = 0; p < 4; p++)
                ldsm4(bf + 4*p, btap + (coB + (uint32_t)p*16) * 128 + byteB[3]);
            #pragma unroll
            for (int mt = 0; mt < 2; mt++)
                #pragma unroll
                for (int n = 0; n < 8; n++)
                    mma16816(acc[mt][n], Ah1[mt][0],Ah1[mt][1],Ah1[mt][2],Ah1[mt][3],
                             bf[(n>>1)*4 + (n&1)*2], bf[(n>>1)*4 + (n&1)*2 + 1]);
        }
        __syncthreads();
    }

    // epilogue: bias + tanh + leaky integrate; also emit h_e_new rows (t=3)
    uint32_t* rowbase = (uint32_t*)(g_Arows + (size_t)3 * (Bn*HW) * 8);
    #pragma unroll
    for (int mt = 0; mt < 2; mt++) {
        #pragma unroll
        for (int half = 0; half < 2; half++) {
            int m  = w*32 + mt*16 + gid + half*8;
            int py = ty0 + (m >> 5);
            int px = tx0 + (m & 31);
            size_t pidx = (size_t)b * CHW + (size_t)py * Ww + px;
            uint32_t* rp = rowbase + ((size_t)b * HW + (size_t)py * Ww + px) * 32;
            #pragma unroll
            for (int n = 0; n < 8; n++) {
                int co = n*8 + 2*tig;
                float a0 = acc[mt][n][half*2]     + g_bcomb[co];
                float a1 = acc[mt][n][half*2 + 1] + g_bcomb[co+1];
                float i0 = g_invtau[co], i1 = g_invtau[co+1];
                float c0 = fast_tanh(a0), c1 = fast_tanh(a1);
                if (co < 32) {
                    float h0 = (i0 < 1.f) ? he[pidx + (size_t)co * HW]     : 0.f;
                    float h1 = (i1 < 1.f) ? he[pidx + (size_t)(co+1) * HW] : 0.f;
                    float v0 = (1.f - i0)*h0 + i0*c0;
                    float v1 = (1.f - i1)*h1 + i1*c1;
                    out[(size_t)NTOT + pidx + (size_t)co * HW]     = v0;
                    out[(size_t)NTOT + pidx + (size_t)(co+1) * HW] = v1;
                    unsigned short h0b, l0b, h1b, l1b;
                    bf16split(v0, h0b, l0b);
                    bf16split(v1, h1b, l1b);
                    int widx = co >> 1;
                    rp[widx]      = (uint32_t)h0b | ((uint32_t)h1b << 16);
                    rp[16 + widx] = (uint32_t)l0b | ((uint32_t)l1b << 16);
                } else {
                    int c = co - 32;
                    float h0 = (i0 < 1.f) ? hi[pidx + (size_t)c * HW]     : 0.f;
                    float h1 = (i1 < 1.f) ? hi[pidx + (size_t)(c+1) * HW] : 0.f;
                    out[(size_t)2*NTOT + pidx + (size_t)c * HW]     = (1.f - i0)*h0 + i0*c0;
                    out[(size_t)2*NTOT + pidx + (size_t)(c+1) * HW] = (1.f - i1)*h1 + i1*c1;
                }
            }
        }
    }
}

// ---------------- out kernel ----------------
__global__ void __launch_bounds__(THREADS)
out_kernel(float* __restrict__ out)
{
    extern __shared__ char sm[];
    const uint32_t smb = smem_u32(sm);
    const int tid  = threadIdx.x;
    const int w    = tid >> 5;
    const int lane = tid & 31;
    const int gid  = lane >> 2;
    const int tig  = lane & 3;
    const int b    = blockIdx.z;
    const int ty0  = blockIdx.y * 16;
    const int tx0  = blockIdx.x * 32;

    float acc[2][4][4];
    #pragma unroll
    for (int mt = 0; mt < 2; mt++)
        #pragma unroll
        for (int n = 0; n < 4; n++)
            #pragma unroll
            for (int q = 0; q < 4; q++) acc[mt][n][q] = 0.f;

    const int lrow = lane & 15;
    const uint32_t lcolA = (uint32_t)((lane >> 4) << 4);
    const int hbase = (w + 1) * 34 + 1;
    const uint32_t coB = (uint32_t)(((lane >> 4) & 1) * 8 + (lane & 7));
    const uint32_t bswz = (uint32_t)(lane & 7) << 4;
    uint32_t byteB[4];
    #pragma unroll
    for (int s = 0; s < 4; s++)
        byteB[s] = (uint32_t)((s*32 + (((lane >> 3) & 1) << 4))) ^ bswz;

    {
        const char* bsrc = (const char*)g_Bout;
        for (int i = tid; i < OU_B_SZ/16; i += THREADS)
            cp16(smb + OU_B_OFF + (uint32_t)i*16, bsrc + (size_t)i*16);
    }
    stage_A(sm, smb, OU_A_OFF, 3, b, ty0, tx0, tid);
    CP_COMMIT();
    CP_WAIT0();
    __syncthreads();

    #pragma unroll 1
    for (int tap = 0; tap < 9; tap++) {
        const int shift = ((tap/3) - 1) * 34 + (tap % 3) - 1;
        const uint32_t btap = smb + OU_B_OFF + (uint32_t)tap * 4096;

        uint32_t abase[2], aswz[2];
        #pragma unroll
        for (int mt = 0; mt < 2; mt++) {
            int row = hbase + shift + mt*16 + lrow;
            abase[mt] = smb + OU_A_OFF + (uint32_t)row * 128;
            aswz[mt]  = (uint32_t)(row & 7) << 4;
        }
        uint32_t Ah0[2][4], Ah1[2][4], At[2][4];
        #pragma unroll
        for (int mt = 0; mt < 2; mt++) {
            ldsm4(Ah0[mt], abase[mt] + ((0u  + lcolA) ^ aswz[mt]));
            ldsm4(Ah1[mt], abase[mt] + ((32u + lcolA) ^ aswz[mt]));
        }

        uint32_t bf[8];
        // B@0
        #pragma unroll
        for (int p = 0; p < 2; p++)
            ldsm4(bf + 4*p, btap + (coB + (uint32_t)p*16) * 128 + byteB[0]);
        #pragma unroll
        for (int mt = 0; mt < 2; mt++)
            #pragma unroll
            for (int n = 0; n < 4; n++)
                mma16816(acc[mt][n], Ah0[mt][0],Ah0[mt][1],Ah0[mt][2],Ah0[mt][3],
                         bf[(n>>1)*4 + (n&1)*2], bf[(n>>1)*4 + (n&1)*2 + 1]);
        #pragma unroll
        for (int mt = 0; mt < 2; mt++)
            ldsm4(At[mt], abase[mt] + ((64u + lcolA) ^ aswz[mt]));
        #pragma unroll
        for (int mt = 0; mt < 2; mt++)
            #pragma unroll
            for (int n = 0; n < 4; n++)
                mma16816(acc[mt][n], At[mt][0],At[mt][1],At[mt][2],At[mt][3],
                         bf[(n>>1)*4 + (n&1)*2], bf[(n>>1)*4 + (n&1)*2 + 1]);
        // B@32
        #pragma unroll
        for (int p = 0; p < 2; p++)
            ldsm4(bf + 4*p, btap + (coB + (uint32_t)p*16) * 128 + byteB[1]);
        #pragma unroll
        for (int mt = 0; mt < 2; mt++)
            #pragma unroll
            for (int n = 0; n < 4; n++)
                mma16816(acc[mt][n], Ah1[mt][0],Ah1[mt][1],Ah1[mt][2],Ah1[mt][3],
                         bf[(n>>1)*4 + (n&1)*2], bf[(n>>1)*4 + (n&1)*2 + 1]);
        #pragma unroll
        for (int mt = 0; mt < 2; mt++)
            ldsm4(At[mt], abase[mt] + ((96u + lcolA) ^ aswz[mt]));
        #pragma unroll
        for (int mt = 0; mt < 2; mt++)
            #pragma unroll
            for (int n = 0; n < 4; n++)
                mma16816(acc[mt][n], At[mt][0],At[mt][1],At[mt][2],At[mt][3],
                         bf[(n>>1)*4 + (n&1)*2], bf[(n>>1)*4 + (n&1)*2 + 1]);
        // B@64
        #pragma unroll
        for (int p = 0; p < 2; p++)
            ldsm4(bf + 4*p, btap + (coB + (uint32_t)p*16) * 128 + byteB[2]);
        #pragma unroll
        for (int mt = 0; mt < 2; mt++)
            #pragma unroll
            for (int n = 0; n < 4; n++)
                mma16816(acc[mt][n], Ah0[mt][0],Ah0[mt][1],Ah0[mt][2],Ah0[mt][3],
                         bf[(n>>1)*4 + (n&1)*2], bf[(n>>1)*4 + (n&1)*2 + 1]);
        // B@96
        #pragma unroll
        for (int p = 0; p < 2; p++)
            ldsm4(bf + 4*p, btap + (coB + (uint32_t)p*16) * 128 + byteB[3]);
        #pragma unroll
        for (int mt = 0; mt < 2; mt++)
            #pragma unroll
            for (int n = 0; n < 4; n++)
                mma16816(acc[mt][n], Ah1[mt][0],Ah1[mt][1],Ah1[mt][2],Ah1[mt][3],
                         bf[(n>>1)*4 + (n&1)*2], bf[(n>>1)*4 + (n&1)*2 + 1]);
    }

    #pragma unroll
    for (int mt = 0; mt < 2; mt++) {
        #pragma unroll
        for (int half = 0; half < 2; half++) {
            int m  = w*32 + mt*16 + gid + half*8;
            int py = ty0 + (m >> 5);
            int px = tx0 + (m & 31);
            size_t pidx = (size_t)b * CHW + (size_t)py * Ww + px;
            #pragma unroll
            for (int n = 0; n < 4; n++) {
                #pragma unroll
                for (int q = 0; q < 2; q++) {
                    int co  = n*8 + 2*tig + q;
                    float v = acc[mt][n][half*2 + q] + g_bout[co];
                    out[pidx + (size_t)co * HW] = fast_tanh(v);
                }
            }
        }
    }
}

extern "C" void kernel_launch(void* const* d_in, const int* in_sizes, int n_in,
                              void* d_out, int out_size)
{
    (void)in_sizes; (void)n_in; (void)out_size;
    const float* x  = (const float*)d_in[0];
    const float* he = (const float*)d_in[1];
    const float* hi = (const float*)d_in[2];
    float* out = (float*)d_out;

    cudaFuncSetAttribute(state_kernel, cudaFuncAttributeMaxDynamicSharedMemorySize, ST_SMEM);
    cudaFuncSetAttribute(out_kernel,   cudaFuncAttributeMaxDynamicSharedMemorySize, OU_SMEM);

    prep_kernel<<<252, 256>>>(
        (const float*)d_in[3],  (const float*)d_in[4],
        (const float*)d_in[5],  (const float*)d_in[6],
        (const float*)d_in[7],  (const float*)d_in[8],
        (const float*)d_in[9],  (const float*)d_in[10],
        (const float*)d_in[11], (const float*)d_in[12],
        (const float*)d_in[13], (const float*)d_in[14],
        (const float*)d_in[15], (const float*)d_in[16],
        (const float*)d_in[17], (const float*)d_in[18]);

    convert_kernel<<<(3*Bn*HW)/256, 256>>>(x, he, hi);

    dim3 grid(4, 8, Bn);   // 32-px x 16-row tiles, batch
    state_kernel<<<grid, THREADS, ST_SMEM>>>(he, hi, out);
    out_kernel<<<grid, THREADS, OU_SMEM>>>(out);
}

// round 8
// speedup vs baseline: 4.9196x; 1.1681x over previous
#include <cuda_runtime.h>
#include <math.h>
#include <stdint.h>

#define Bn 16
#define Cc 32
#define Hh 128
#define Ww 128
#define HW (Hh*Ww)
#define CHW (Cc*HW)
#define NTOT (Bn*CHW)

// block tile: 8 out rows x 32 out cols = 256 px; halo 10x34 = 340 A rows
#define THREADS 256
#define NROWS 340

#define B_OFF  0
#define B_SZ   36864                 // 9 taps * 32 co * 128B
#define A_OFF  B_SZ
#define A_SZ   (NROWS*128)           // 43520
#define SMEM_T (B_SZ + A_SZ)         // 80384 -> 2 blocks/SM

// global A-row images: [t(4)][b*HW + pix] rows of 128B ([hi 32ci | lo 32ci] bf16)
__device__ uint4 g_Arows[(size_t)4*Bn*HW*8];

__device__ __align__(16) unsigned short g_Bst[3*36864];  // pre-swizzled B, 3 x 73728 B
__device__ __align__(16) unsigned short g_Bout[18432];   // pre-swizzled B_out (36864 B)
__device__ float g_bcomb[64];
__device__ float g_bout[32];
__device__ float g_invtau[64];

// ---------------- helpers ----------------
__device__ __forceinline__ uint32_t smem_u32(const void* p) {
    uint32_t a;
    asm("{ .reg .u64 t; cvta.to.shared.u64 t, %1; cvt.u32.u64 %0, t; }" : "=r"(a) : "l"(p));
    return a;
}
__device__ __forceinline__ void bf16split(float v, unsigned short& h, unsigned short& l) {
    asm("cvt.rn.bf16.f32 %0, %1;" : "=h"(h) : "f"(v));
    float hf;
    asm("cvt.f32.bf16 %0, %1;" : "=f"(hf) : "h"(h));
    asm("cvt.rn.bf16.f32 %0, %1;" : "=h"(l) : "f"(v - hf));
}
__device__ __forceinline__ float fast_tanh(float x) {
    float e, r;
    asm("ex2.approx.f32 %0, %1;" : "=f"(e) : "f"(x * 2.8853900817779268f));
    asm("rcp.approx.f32 %0, %1;" : "=f"(r) : "f"(e + 1.f));
    return fmaf(-2.f, r, 1.f);
}
__device__ __forceinline__ void mma16816(float* c,
    uint32_t a0, uint32_t a1, uint32_t a2, uint32_t a3, uint32_t b0, uint32_t b1)
{
    asm volatile(
        "mma.sync.aligned.m16n8k16.row.col.f32.bf16.bf16.f32 "
        "{%0,%1,%2,%3}, {%4,%5,%6,%7}, {%8,%9}, {%0,%1,%2,%3};"
        : "+f"(c[0]), "+f"(c[1]), "+f"(c[2]), "+f"(c[3])
        : "r"(a0), "r"(a1), "r"(a2), "r"(a3), "r"(b0), "r"(b1));
}
__device__ __forceinline__ void ldsm4(uint32_t* r, uint32_t addr) {
    asm volatile("ldmatrix.sync.aligned.m8n8.x4.shared.b16 {%0,%1,%2,%3}, [%4];"
        : "=r"(r[0]), "=r"(r[1]), "=r"(r[2]), "=r"(r[3]) : "r"(addr));
}
__device__ __forceinline__ void cp16(uint32_t smdst, const void* gsrc) {
    asm volatile("cp.async.cg.shared.global [%0], [%1], 16;" :: "r"(smdst), "l"(gsrc));
}
#define CP_COMMIT() asm volatile("cp.async.commit_group;" ::: "memory")
#define CP_WAIT0()  asm volatile("cp.async.wait_group 0;" ::: "memory")

// ---------------- prep ----------------
__global__ void prep_kernel(
    const float* __restrict__ W_in_e, const float* __restrict__ b_in_e,
    const float* __restrict__ W_in_i, const float* __restrict__ b_in_i,
    const float* __restrict__ W_e_e,  const float* __restrict__ b_e_e,
    const float* __restrict__ W_e_i,  const float* __restrict__ b_e_i,
    const float* __restrict__ W_e_out,const float* __restrict__ b_e_out,
    const float* __restrict__ W_i_e,  const float* __restrict__ b_i_e,
    const float* __restrict__ W_i_i,  const float* __restrict__ b_i_i,
    const float* __restrict__ tau_e,  const float* __restrict__ tau_i)
{
    int fid = blockIdx.x * 256 + threadIdx.x;
    if (fid < 3*9*64*32) {
        int ci  = fid & 31;
        int r   = fid >> 5;
        int co  = r & 63;  r >>= 6;
        int tau = r % 9;
        int t   = r / 9;
        int src = (co & 31) * 288 + ci * 9 + tau;   // OIHW
        float w;
        if (t == 0)      w = (co < 32) ? W_in_e[src] : W_in_i[src];
        else if (t == 1) w = fmaxf((co < 32) ? W_e_e[src] : W_e_i[src], 0.f);
        else             w = -fmaxf((co < 32) ? W_i_e[src] : W_i_i[src], 0.f);
        unsigned short h, l;
        bf16split(w, h, l);
        uint32_t base = (uint32_t)t*73728 + (uint32_t)tau*8192 + (uint32_t)co*128;
        uint32_t swz  = (uint32_t)(co & 7) << 4;
        g_Bst[(base + (((uint32_t)ci*2)       ^ swz)) >> 1] = h;
        g_Bst[(base + ((64u + (uint32_t)ci*2) ^ swz)) >> 1] = l;
    } else if (fid < 3*9*64*32 + 9*32*32) {
        int f2  = fid - 3*9*64*32;
        int ci  = f2 & 31;
        int r   = f2 >> 5;
        int co  = r & 31;
        int tau = r >> 5;
        float w = fmaxf(W_e_out[co*288 + ci*9 + tau], 0.f);
        unsigned short h, l;
        bf16split(w, h, l);
        uint32_t base = (uint32_t)tau*4096 + (uint32_t)co*128;
        uint32_t swz  = (uint32_t)(co & 7) << 4;
        g_Bout[(base + (((uint32_t)ci*2)       ^ swz)) >> 1] = h;
        g_Bout[(base + ((64u + (uint32_t)ci*2) ^ swz)) >> 1] = l;
    }
    if (blockIdx.x == 0 && threadIdx.x < 64) {
        int co = threadIdx.x;
        if (co < 32) {
            g_bcomb[co]  = b_in_e[co] + fmaxf(b_e_e[co], 0.f) - fmaxf(b_i_e[co], 0.f);
            g_invtau[co] = 1.f / fmaxf(tau_e[co], 1.f);
            g_bout[co]   = fmaxf(b_e_out[co], 0.f);
        } else {
            int c = co - 32;
            g_bcomb[co]  = b_in_i[c] + fmaxf(b_e_i[c], 0.f) - fmaxf(b_i_i[c], 0.f);
            g_invtau[co] = 1.f / fmaxf(tau_i[c], 1.f);
        }
    }
}

// ---------------- convert: NCHW fp32 -> per-pixel 128B bf16 hi/lo rows ----------------
__global__ void __launch_bounds__(256)
convert_kernel(const float* __restrict__ x, const float* __restrict__ he,
               const float* __restrict__ hi)
{
    int gidx = blockIdx.x * 256 + threadIdx.x;
    int t = gidx / (Bn*HW);
    int p = gidx - t * (Bn*HW);
    int b = p / HW;
    int pix = p - b * HW;
    const float* src = (t == 0 ? x : (t == 1 ? he : hi)) + (size_t)b * CHW + pix;
    uint4* dst = g_Arows + ((size_t)t * (Bn*HW) + p) * 8;

    uint32_t hw[16], lw[16];
    #pragma unroll
    for (int k = 0; k < 16; k++) {
        float v0 = src[(size_t)(2*k)   * HW];
        float v1 = src[(size_t)(2*k+1) * HW];
        unsigned short h0, l0, h1, l1;
        bf16split(v0, h0, l0);
        bf16split(v1, h1, l1);
        hw[k] = (uint32_t)h0 | ((uint32_t)h1 << 16);
        lw[k] = (uint32_t)l0 | ((uint32_t)l1 << 16);
    }
    #pragma unroll
    for (int j = 0; j < 4; j++) {
        dst[j]     = make_uint4(hw[4*j], hw[4*j+1], hw[4*j+2], hw[4*j+3]);
        dst[4 + j] = make_uint4(lw[4*j], lw[4*j+1], lw[4*j+2], lw[4*j+3]);
    }
}

// A tile copy (cp.async, zero halo), 8-row tile
__device__ __forceinline__ void stage_A(char* sm, uint32_t smb,
                                        int t, int b, int ty0, int tx0, int tid)
{
    const char* gbase = (const char*)g_Arows + ((size_t)t * (Bn*HW) + (size_t)b * HW) * 128;
    for (int i = tid; i < NROWS*8; i += THREADS) {
        int r = i >> 3, c = i & 7;
        int ry = r / 34, rx = r - ry*34;
        int gy = ty0 + ry - 1, gx = tx0 + rx - 1;
        uint32_t dst = smb + A_OFF + (uint32_t)r*128
                     + (((uint32_t)c*16) ^ ((uint32_t)(r & 7) << 4));
        if (((unsigned)gy < 128u) && ((unsigned)gx < 128u))
            cp16(dst, gbase + ((size_t)(gy*128 + gx))*128 + c*16);
        else
            *(uint4*)(sm + (dst - smb)) = make_uint4(0,0,0,0);
    }
}

// shared mainloop body: N=32, 9 taps, fragment reuse; acc[2][4][4]
__device__ __forceinline__ void conv_tap_loop(
    const uint32_t smb, float acc[2][4][4],
    const int hbase, const int lrow, const uint32_t lcolA,
    const uint32_t coB, const uint32_t* byteB)
{
    #pragma unroll 1
    for (int tap = 0; tap < 9; tap++) {
        const int shift = ((tap/3) - 1) * 34 + (tap % 3) - 1;
        const uint32_t btap = smb + B_OFF + (uint32_t)tap * 4096;

        uint32_t abase[2], aswz[2];
        #pragma unroll
        for (int mt = 0; mt < 2; mt++) {
            int row = hbase + shift + mt*16 + lrow;
            abase[mt] = smb + A_OFF + (uint32_t)row * 128;
            aswz[mt]  = (uint32_t)(row & 7) << 4;
        }
        uint32_t Ah0[2][4], Ah1[2][4], At[2][4];
        #pragma unroll
        for (int mt = 0; mt < 2; mt++) {
            ldsm4(Ah0[mt], abase[mt] + ((0u  + lcolA) ^ aswz[mt]));
            ldsm4(Ah1[mt], abase[mt] + ((32u + lcolA) ^ aswz[mt]));
        }

        uint32_t bf[8];
        // B@0 (Whi k0-15): hi step0, lo step0
        #pragma unroll
        for (int p = 0; p < 2; p++)
            ldsm4(bf + 4*p, btap + (coB + (uint32_t)p*16) * 128 + byteB[0]);
        #pragma unroll
        for (int mt = 0; mt < 2; mt++)
            #pragma unroll
            for (int n = 0; n < 4; n++)
                mma16816(acc[mt][n], Ah0[mt][0],Ah0[mt][1],Ah0[mt][2],Ah0[mt][3],
                         bf[(n>>1)*4 + (n&1)*2], bf[(n>>1)*4 + (n&1)*2 + 1]);
        #pragma unroll
        for (int mt = 0; mt < 2; mt++)
            ldsm4(At[mt], abase[mt] + ((64u + lcolA) ^ aswz[mt]));
        #pragma unroll
        for (int mt = 0; mt < 2; mt++)
            #pragma unroll
            for (int n = 0; n < 4; n++)
                mma16816(acc[mt][n], At[mt][0],At[mt][1],At[mt][2],At[mt][3],
                         bf[(n>>1)*4 + (n&1)*2], bf[(n>>1)*4 + (n&1)*2 + 1]);
        // B@32 (Whi k16-31): hi step1, lo step1
        #pragma unroll
        for (int p = 0; p < 2; p++)
            ldsm4(bf + 4*p, btap + (coB + (uint32_t)p*16) * 128 + byteB[1]);
        #pragma unroll
        for (int mt = 0; mt < 2; mt++)
            #pragma unroll
            for (int n = 0; n < 4; n++)
                mma16816(acc[mt][n], Ah1[mt][0],Ah1[mt][1],Ah1[mt][2],Ah1[mt][3],
                         bf[(n>>1)*4 + (n&1)*2], bf[(n>>1)*4 + (n&1)*2 + 1]);
        #pragma unroll
        for (int mt = 0; mt < 2; mt++)
            ldsm4(At[mt], abase[mt] + ((96u + lcolA) ^ aswz[mt]));
        #pragma unroll
        for (int mt = 0; mt < 2; mt++)
            #pragma unroll
            for (int n = 0; n < 4; n++)
                mma16816(acc[mt][n], At[mt][0],At[mt][1],At[mt][2],At[mt][3],
                         bf[(n>>1)*4 + (n&1)*2], bf[(n>>1)*4 + (n&1)*2 + 1]);
        // B@64 (Wlo k0-15): hi step0
        #pragma unroll
        for (int p = 0; p < 2; p++)
            ldsm4(bf + 4*p, btap + (coB + (uint32_t)p*16) * 128 + byteB[2]);
        #pragma unroll
        for (int mt = 0; mt < 2; mt++)
            #pragma unroll
            for (int n = 0; n < 4; n++)
                mma16816(acc[mt][n], Ah0[mt][0],Ah0[mt][1],Ah0[mt][2],Ah0[mt][3],
                         bf[(n>>1)*4 + (n&1)*2], bf[(n>>1)*4 + (n&1)*2 + 1]);
        // B@96 (Wlo k16-31): hi step1
        #pragma unroll
        for (int p = 0; p < 2; p++)
            ldsm4(bf + 4*p, btap + (coB + (uint32_t)p*16) * 128 + byteB[3]);
        #pragma unroll
        for (int mt = 0; mt < 2; mt++)
            #pragma unroll
            for (int n = 0; n < 4; n++)
                mma16816(acc[mt][n], Ah1[mt][0],Ah1[mt][1],Ah1[mt][2],Ah1[mt][3],
                         bf[(n>>1)*4 + (n&1)*2], bf[(n>>1)*4 + (n&1)*2 + 1]);
    }
}

// ---------------- state kernel (N-split: half=0 -> e channels, 1 -> i) ----------------
__global__ void __launch_bounds__(THREADS)
state_kernel(const float* __restrict__ he, const float* __restrict__ hi,
             float* __restrict__ out)
{
    extern __shared__ char sm[];
    const uint32_t smb = smem_u32(sm);
    const int tid  = threadIdx.x;
    const int w    = tid >> 5;
    const int lane = tid & 31;
    const int gid  = lane >> 2;
    const int tig  = lane & 3;
    const int b    = blockIdx.z >> 1;
    const int half = blockIdx.z & 1;
    const int ty0  = blockIdx.y * 8;
    const int tx0  = blockIdx.x * 32;

    float acc[2][4][4];
    #pragma unroll
    for (int mt = 0; mt < 2; mt++)
        #pragma unroll
        for (int n = 0; n < 4; n++)
            #pragma unroll
            for (int q = 0; q < 4; q++) acc[mt][n][q] = 0.f;

    const int lrow = lane & 15;
    const uint32_t lcolA = (uint32_t)((lane >> 4) << 4);
    const int hbase = (w + 1) * 34 + 1;
    const uint32_t coB = (uint32_t)(((lane >> 4) & 1) * 8 + (lane & 7));
    const uint32_t bswz = (uint32_t)(lane & 7) << 4;
    uint32_t byteB[4];
    #pragma unroll
    for (int s = 0; s < 4; s++)
        byteB[s] = (uint32_t)((s*32 + (((lane >> 3) & 1) << 4))) ^ bswz;

    for (int t = 0; t < 3; t++) {
        // B: this co-half only (pre-swizzled contiguous 4096B per tap)
        {
            const char* bsrc = (const char*)g_Bst + (size_t)t * 73728 + (size_t)half * 4096;
            for (int i = tid; i < B_SZ/16; i += THREADS) {
                int tap = i >> 8, within = i & 255;
                cp16(smb + B_OFF + (uint32_t)i*16,
                     bsrc + (size_t)tap*8192 + (size_t)within*16);
            }
        }
        stage_A(sm, smb, t, b, ty0, tx0, tid);
        CP_COMMIT();
        CP_WAIT0();
        __syncthreads();

        conv_tap_loop(smb, acc, hbase, lrow, lcolA, coB, byteB);
        __syncthreads();
    }

    // epilogue
    uint32_t* rowbase = (uint32_t*)(g_Arows + (size_t)3 * (Bn*HW) * 8);
    #pragma unroll
    for (int mt = 0; mt < 2; mt++) {
        #pragma unroll
        for (int hf = 0; hf < 2; hf++) {
            int px_local = mt*16 + gid + hf*8;
            int py = ty0 + w;
            int px = tx0 + px_local;
            size_t pidx = (size_t)b * CHW + (size_t)py * Ww + px;
            uint32_t* rp = rowbase + ((size_t)b * HW + (size_t)py * Ww + px) * 32;
            #pragma unroll
            for (int n = 0; n < 4; n++) {
                int cl = n*8 + 2*tig;             // local co pair (cl, cl+1)
                int co = half*32 + cl;
                float a0 = acc[mt][n][hf*2]     + g_bcomb[co];
                float a1 = acc[mt][n][hf*2 + 1] + g_bcomb[co+1];
                float i0 = g_invtau[co], i1 = g_invtau[co+1];
                float c0 = fast_tanh(a0), c1 = fast_tanh(a1);
                if (half == 0) {
                    float h0 = (i0 < 1.f) ? he[pidx + (size_t)cl * HW]     : 0.f;
                    float h1 = (i1 < 1.f) ? he[pidx + (size_t)(cl+1) * HW] : 0.f;
                    float v0 = (1.f - i0)*h0 + i0*c0;
                    float v1 = (1.f - i1)*h1 + i1*c1;
                    out[(size_t)NTOT + pidx + (size_t)cl * HW]     = v0;
                    out[(size_t)NTOT + pidx + (size_t)(cl+1) * HW] = v1;
                    unsigned short h0b, l0b, h1b, l1b;
                    bf16split(v0, h0b, l0b);
                    bf16split(v1, h1b, l1b);
                    int widx = cl >> 1;
                    rp[widx]      = (uint32_t)h0b | ((uint32_t)h1b << 16);
                    rp[16 + widx] = (uint32_t)l0b | ((uint32_t)l1b << 16);
                } else {
                    float h0 = (i0 < 1.f) ? hi[pidx + (size_t)cl * HW]     : 0.f;
                    float h1 = (i1 < 1.f) ? hi[pidx + (size_t)(cl+1) * HW] : 0.f;
                    out[(size_t)2*NTOT + pidx + (size_t)cl * HW]     = (1.f - i0)*h0 + i0*c0;
                    out[(size_t)2*NTOT + pidx + (size_t)(cl+1) * HW] = (1.f - i1)*h1 + i1*c1;
                }
            }
        }
    }
}

// ---------------- out kernel ----------------
__global__ void __launch_bounds__(THREADS)
out_kernel(float* __restrict__ out)
{
    extern __shared__ char sm[];
    const uint32_t smb = smem_u32(sm);
    const int tid  = threadIdx.x;
    const int w    = tid >> 5;
    const int lane = tid & 31;
    const int gid  = lane >> 2;
    const int tig  = lane & 3;
    const int b    = blockIdx.z;
    const int ty0  = blockIdx.y * 8;
    const int tx0  = blockIdx.x * 32;

    float acc[2][4][4];
    #pragma unroll
    for (int mt = 0; mt < 2; mt++)
        #pragma unroll
        for (int n = 0; n < 4; n++)
            #pragma unroll
            for (int q = 0; q < 4; q++) acc[mt][n][q] = 0.f;

    const int lrow = lane & 15;
    const uint32_t lcolA = (uint32_t)((lane >> 4) << 4);
    const int hbase = (w + 1) * 34 + 1;
    const uint32_t coB = (uint32_t)(((lane >> 4) & 1) * 8 + (lane & 7));
    const uint32_t bswz = (uint32_t)(lane & 7) << 4;
    uint32_t byteB[4];
    #pragma unroll
    for (int s = 0; s < 4; s++)
        byteB[s] = (uint32_t)((s*32 + (((lane >> 3) & 1) << 4))) ^ bswz;

    {
        const char* bsrc = (const char*)g_Bout;
        for (int i = tid; i < B_SZ/16; i += THREADS)
            cp16(smb + B_OFF + (uint32_t)i*16, bsrc + (size_t)i*16);
    }
    stage_A(sm, smb, 3, b, ty0, tx0, tid);
    CP_COMMIT();
    CP_WAIT0();
    __syncthreads();

    conv_tap_loop(smb, acc, hbase, lrow, lcolA, coB, byteB);

    #pragma unroll
    for (int mt = 0; mt < 2; mt++) {
        #pragma unroll
        for (int hf = 0; hf < 2; hf++) {
            int px_local = mt*16 + gid + hf*8;
            int py = ty0 + w;
            int px = tx0 + px_local;
            size_t pidx = (size_t)b * CHW + (size_t)py * Ww + px;
            #pragma unroll
            for (int n = 0; n < 4; n++) {
                #pragma unroll
                for (int q = 0; q < 2; q++) {
                    int co  = n*8 + 2*tig + q;
                    float v = acc[mt][n][hf*2 + q] + g_bout[co];
                    out[pidx + (size_t)co * HW] = fast_tanh(v);
                }
            }
        }
    }
}

extern "C" void kernel_launch(void* const* d_in, const int* in_sizes, int n_in,
                              void* d_out, int out_size)
{
    (void)in_sizes; (void)n_in; (void)out_size;
    const float* x  = (const float*)d_in[0];
    const float* he = (const float*)d_in[1];
    const float* hi = (const float*)d_in[2];
    float* out = (float*)d_out;

    cudaFuncSetAttribute(state_kernel, cudaFuncAttributeMaxDynamicSharedMemorySize, SMEM_T);
    cudaFuncSetAttribute(out_kernel,   cudaFuncAttributeMaxDynamicSharedMemorySize, SMEM_T);

    prep_kernel<<<252, 256>>>(
        (const float*)d_in[3],  (const float*)d_in[4],
        (const float*)d_in[5],  (const float*)d_in[6],
        (const float*)d_in[7],  (const float*)d_in[8],
        (const float*)d_in[9],  (const float*)d_in[10],
        (const float*)d_in[11], (const float*)d_in[12],
        (const float*)d_in[13], (const float*)d_in[14],
        (const float*)d_in[15], (const float*)d_in[16],
        (const float*)d_in[17], (const float*)d_in[18]);

    convert_kernel<<<(3*Bn*HW)/256, 256>>>(x, he, hi);

    dim3 gs(4, 16, Bn*2);   // x-tiles, y-tiles, batch x co-half
    state_kernel<<<gs, THREADS, SMEM_T>>>(he, hi, out);
    dim3 go(4, 16, Bn);
    out_kernel<<<go, THREADS, SMEM_T>>>(out);
}

// round 9
// speedup vs baseline: 4.9392x; 1.0040x over previous
#include <cuda_runtime.h>
#include <math.h>
#include <stdint.h>

#define Bn 16
#define Cc 32
#define Hh 128
#define Ww 128
#define HW (Hh*Ww)
#define CHW (Cc*HW)
#define NTOT (Bn*CHW)

// block tile: 8 out rows x 32 out cols = 256 px; halo 10x34 = 340 A rows
#define THREADS 256
#define NROWS 340

#define RS     144                    // padded SMEM row stride (128 data + 16)
#define B_TAP  (32*RS)                // 4608
#define B_SZ   (9*B_TAP)              // 41472
#define B_OFF  0
#define A_OFF  B_SZ
#define A_SZ   (NROWS*RS)             // 48960
#define SMEM_T (B_SZ + A_SZ)          // 90432 -> 2 blocks/SM

// global A-row images: [t(4)][b*HW + pix] rows of 128B ([hi 32ci | lo 32ci] bf16), dense
__device__ uint4 g_Arows[(size_t)4*Bn*HW*8];

// B in padded-dense layout: state [t(3)][half(2)][tap(9)][co(32)][144B]; out [tap][co][144B]
__device__ __align__(16) unsigned short g_Bst[3*2*20736];   // 3*82944 B
__device__ __align__(16) unsigned short g_Bout[20736];      // 41472 B
__device__ float g_bcomb[64];
__device__ float g_bout[32];
__device__ float g_invtau[64];

// ---------------- helpers ----------------
__device__ __forceinline__ uint32_t smem_u32(const void* p) {
    uint32_t a;
    asm("{ .reg .u64 t; cvta.to.shared.u64 t, %1; cvt.u32.u64 %0, t; }" : "=r"(a) : "l"(p));
    return a;
}
__device__ __forceinline__ void bf16split(float v, unsigned short& h, unsigned short& l) {
    asm("cvt.rn.bf16.f32 %0, %1;" : "=h"(h) : "f"(v));
    float hf;
    asm("cvt.f32.bf16 %0, %1;" : "=f"(hf) : "h"(h));
    asm("cvt.rn.bf16.f32 %0, %1;" : "=h"(l) : "f"(v - hf));
}
__device__ __forceinline__ float fast_tanh(float x) {
    float e, r;
    asm("ex2.approx.f32 %0, %1;" : "=f"(e) : "f"(x * 2.8853900817779268f));
    asm("rcp.approx.f32 %0, %1;" : "=f"(r) : "f"(e + 1.f));
    return fmaf(-2.f, r, 1.f);
}
__device__ __forceinline__ void mma16816(float* c,
    uint32_t a0, uint32_t a1, uint32_t a2, uint32_t a3, uint32_t b0, uint32_t b1)
{
    asm volatile(
        "mma.sync.aligned.m16n8k16.row.col.f32.bf16.bf16.f32 "
        "{%0,%1,%2,%3}, {%4,%5,%6,%7}, {%8,%9}, {%0,%1,%2,%3};"
        : "+f"(c[0]), "+f"(c[1]), "+f"(c[2]), "+f"(c[3])
        : "r"(a0), "r"(a1), "r"(a2), "r"(a3), "r"(b0), "r"(b1));
}
__device__ __forceinline__ void ldsm4(uint32_t* r, uint32_t addr) {
    asm volatile("ldmatrix.sync.aligned.m8n8.x4.shared.b16 {%0,%1,%2,%3}, [%4];"
        : "=r"(r[0]), "=r"(r[1]), "=r"(r[2]), "=r"(r[3]) : "r"(addr));
}
__device__ __forceinline__ void cp16(uint32_t smdst, const void* gsrc) {
    asm volatile("cp.async.cg.shared.global [%0], [%1], 16;" :: "r"(smdst), "l"(gsrc));
}
#define CP_COMMIT() asm volatile("cp.async.commit_group;" ::: "memory")
#define CP_WAIT0()  asm volatile("cp.async.wait_group 0;" ::: "memory")

// ---------------- prep ----------------
__global__ void prep_kernel(
    const float* __restrict__ W_in_e, const float* __restrict__ b_in_e,
    const float* __restrict__ W_in_i, const float* __restrict__ b_in_i,
    const float* __restrict__ W_e_e,  const float* __restrict__ b_e_e,
    const float* __restrict__ W_e_i,  const float* __restrict__ b_e_i,
    const float* __restrict__ W_e_out,const float* __restrict__ b_e_out,
    const float* __restrict__ W_i_e,  const float* __restrict__ b_i_e,
    const float* __restrict__ W_i_i,  const float* __restrict__ b_i_i,
    const float* __restrict__ tau_e,  const float* __restrict__ tau_i)
{
    int fid = blockIdx.x * 256 + threadIdx.x;
    if (fid < 3*9*64*32) {
        int ci  = fid & 31;
        int r   = fid >> 5;
        int co  = r & 63;  r >>= 6;
        int tau = r % 9;
        int t   = r / 9;
        int src = (co & 31) * 288 + ci * 9 + tau;   // OIHW
        float w;
        if (t == 0)      w = (co < 32) ? W_in_e[src] : W_in_i[src];
        else if (t == 1) w = fmaxf((co < 32) ? W_e_e[src] : W_e_i[src], 0.f);
        else             w = -fmaxf((co < 32) ? W_i_e[src] : W_i_i[src], 0.f);
        unsigned short h, l;
        bf16split(w, h, l);
        uint32_t base = (uint32_t)t*82944 + (uint32_t)(co >> 5)*41472
                      + (uint32_t)tau*B_TAP + (uint32_t)(co & 31)*RS;
        g_Bst[(base + (uint32_t)ci*2) >> 1]       = h;   // hi bytes [0,64)
        g_Bst[(base + 64u + (uint32_t)ci*2) >> 1] = l;   // lo bytes [64,128)
    } else if (fid < 3*9*64*32 + 9*32*32) {
        int f2  = fid - 3*9*64*32;
        int ci  = f2 & 31;
        int r   = f2 >> 5;
        int co  = r & 31;
        int tau = r >> 5;
        float w = fmaxf(W_e_out[co*288 + ci*9 + tau], 0.f);
        unsigned short h, l;
        bf16split(w, h, l);
        uint32_t base = (uint32_t)tau*B_TAP + (uint32_t)co*RS;
        g_Bout[(base + (uint32_t)ci*2) >> 1]       = h;
        g_Bout[(base + 64u + (uint32_t)ci*2) >> 1] = l;
    }
    if (blockIdx.x == 0 && threadIdx.x < 64) {
        int co = threadIdx.x;
        if (co < 32) {
            g_bcomb[co]  = b_in_e[co] + fmaxf(b_e_e[co], 0.f) - fmaxf(b_i_e[co], 0.f);
            g_invtau[co] = 1.f / fmaxf(tau_e[co], 1.f);
            g_bout[co]   = fmaxf(b_e_out[co], 0.f);
        } else {
            int c = co - 32;
            g_bcomb[co]  = b_in_i[c] + fmaxf(b_e_i[c], 0.f) - fmaxf(b_i_i[c], 0.f);
            g_invtau[co] = 1.f / fmaxf(tau_i[c], 1.f);
        }
    }
}

// ---------------- convert: NCHW fp32 -> per-pixel 128B bf16 hi/lo rows ----------------
__global__ void __launch_bounds__(256)
convert_kernel(const float* __restrict__ x, const float* __restrict__ he,
               const float* __restrict__ hi)
{
    int gidx = blockIdx.x * 256 + threadIdx.x;
    int t = gidx / (Bn*HW);
    int p = gidx - t * (Bn*HW);
    int b = p / HW;
    int pix = p - b * HW;
    const float* src = (t == 0 ? x : (t == 1 ? he : hi)) + (size_t)b * CHW + pix;
    uint4* dst = g_Arows + ((size_t)t * (Bn*HW) + p) * 8;

    uint32_t hw[16], lw[16];
    #pragma unroll
    for (int k = 0; k < 16; k++) {
        float v0 = src[(size_t)(2*k)   * HW];
        float v1 = src[(size_t)(2*k+1) * HW];
        unsigned short h0, l0, h1, l1;
        bf16split(v0, h0, l0);
        bf16split(v1, h1, l1);
        hw[k] = (uint32_t)h0 | ((uint32_t)h1 << 16);
        lw[k] = (uint32_t)l0 | ((uint32_t)l1 << 16);
    }
    #pragma unroll
    for (int j = 0; j < 4; j++) {
        dst[j]     = make_uint4(hw[4*j], hw[4*j+1], hw[4*j+2], hw[4*j+3]);
        dst[4 + j] = make_uint4(lw[4*j], lw[4*j+1], lw[4*j+2], lw[4*j+3]);
    }
}

// A tile copy (cp.async, zero halo), padded-dense SMEM rows
__device__ __forceinline__ void stage_A(char* sm, uint32_t smb,
                                        int t, int b, int ty0, int tx0, int tid)
{
    const char* gbase = (const char*)g_Arows + ((size_t)t * (Bn*HW) + (size_t)b * HW) * 128;
    for (int i = tid; i < NROWS*8; i += THREADS) {
        int r = i >> 3, c = i & 7;
        int ry = r / 34, rx = r - ry*34;
        int gy = ty0 + ry - 1, gx = tx0 + rx - 1;
        uint32_t dst = smb + A_OFF + (uint32_t)r*RS + (uint32_t)c*16;
        if (((unsigned)gy < 128u) && ((unsigned)gx < 128u))
            cp16(dst, gbase + ((size_t)(gy*128 + gx))*128 + c*16);
        else
            *(uint4*)(sm + (dst - smb)) = make_uint4(0,0,0,0);
    }
}

// mainloop body: N=32, 9 taps; tap-invariant lane bases, immediate offsets
__device__ __forceinline__ void conv_tap_loop(
    float acc[2][4][4], const uint32_t laneA0, const uint32_t laneA1, const uint32_t laneB)
{
    #pragma unroll 1
    for (int tap = 0; tap < 9; tap++) {
        const int soff = ((tap/3) - 1) * (34*RS) + ((tap % 3) - 1) * RS;
        const uint32_t aA0 = laneA0 + soff;
        const uint32_t aA1 = laneA1 + soff;
        const uint32_t bB  = laneB + (uint32_t)tap * B_TAP;

        // fragment burst: 8 A + 8 B ldsm4 (offsets fold into LDSM immediates)
        uint32_t Ah0[2][4], Ah1[2][4], Al0[2][4], Al1[2][4];
        ldsm4(Ah0[0], aA0 + 0);  ldsm4(Ah1[0], aA0 + 32);
        ldsm4(Al0[0], aA0 + 64); ldsm4(Al1[0], aA0 + 96);
        ldsm4(Ah0[1], aA1 + 0);  ldsm4(Ah1[1], aA1 + 32);
        ldsm4(Al0[1], aA1 + 64); ldsm4(Al1[1], aA1 + 96);

        uint32_t bf0[8], bf1[8], bf2[8], bf3[8];
        ldsm4(bf0,     bB + 0);          ldsm4(bf0 + 4, bB + 2304 + 0);
        ldsm4(bf1,     bB + 32);         ldsm4(bf1 + 4, bB + 2304 + 32);
        ldsm4(bf2,     bB + 64);         ldsm4(bf2 + 4, bB + 2304 + 64);
        ldsm4(bf3,     bB + 96);         ldsm4(bf3 + 4, bB + 2304 + 96);

        #pragma unroll
        for (int mt = 0; mt < 2; mt++)
            #pragma unroll
            for (int n = 0; n < 4; n++) {
                const int i0 = (n>>1)*4 + (n&1)*2;
                mma16816(acc[mt][n], Ah0[mt][0],Ah0[mt][1],Ah0[mt][2],Ah0[mt][3], bf0[i0], bf0[i0+1]);
                mma16816(acc[mt][n], Al0[mt][0],Al0[mt][1],Al0[mt][2],Al0[mt][3], bf0[i0], bf0[i0+1]);
                mma16816(acc[mt][n], Ah1[mt][0],Ah1[mt][1],Ah1[mt][2],Ah1[mt][3], bf1[i0], bf1[i0+1]);
                mma16816(acc[mt][n], Al1[mt][0],Al1[mt][1],Al1[mt][2],Al1[mt][3], bf1[i0], bf1[i0+1]);
                mma16816(acc[mt][n], Ah0[mt][0],Ah0[mt][1],Ah0[mt][2],Ah0[mt][3], bf2[i0], bf2[i0+1]);
                mma16816(acc[mt][n], Ah1[mt][0],Ah1[mt][1],Ah1[mt][2],Ah1[mt][3], bf3[i0], bf3[i0+1]);
            }
    }
}

// ---------------- state kernel (N-split: half=0 -> e channels, 1 -> i) ----------------
__global__ void __launch_bounds__(THREADS, 2)
state_kernel(const float* __restrict__ he, const float* __restrict__ hi,
             float* __restrict__ out)
{
    extern __shared__ char sm[];
    const uint32_t smb = smem_u32(sm);
    const int tid  = threadIdx.x;
    const int w    = tid >> 5;
    const int lane = tid & 31;
    const int gid  = lane >> 2;
    const int tig  = lane & 3;
    const int b    = blockIdx.z >> 1;
    const int half = blockIdx.z & 1;
    const int ty0  = blockIdx.y * 8;
    const int tx0  = blockIdx.x * 32;

    float acc[2][4][4];
    #pragma unroll
    for (int mt = 0; mt < 2; mt++)
        #pragma unroll
        for (int n = 0; n < 4; n++)
            #pragma unroll
            for (int q = 0; q < 4; q++) acc[mt][n][q] = 0.f;

    // tap-invariant lane base addresses
    const int hbase = (w + 1) * 34 + 1;
    const uint32_t laneA0 = smb + A_OFF + (uint32_t)(hbase + (lane & 15)) * RS
                          + (uint32_t)((lane >> 4) << 4);
    const uint32_t laneA1 = laneA0 + 16u*RS;
    const uint32_t laneB  = smb + B_OFF
                          + (uint32_t)((((lane >> 4) & 1)*8 + (lane & 7))) * RS
                          + (uint32_t)(((lane >> 3) & 1) << 4);

    for (int t = 0; t < 3; t++) {
        {
            const char* bsrc = (const char*)g_Bst + (size_t)t*82944 + (size_t)half*41472;
            for (int i = tid; i < B_SZ/16; i += THREADS)
                cp16(smb + B_OFF + (uint32_t)i*16, bsrc + (size_t)i*16);
        }
        stage_A(sm, smb, t, b, ty0, tx0, tid);
        CP_COMMIT();
        CP_WAIT0();
        __syncthreads();

        conv_tap_loop(acc, laneA0, laneA1, laneB);
        __syncthreads();
    }

    // epilogue
    uint32_t* rowbase = (uint32_t*)(g_Arows + (size_t)3 * (Bn*HW) * 8);
    #pragma unroll
    for (int mt = 0; mt < 2; mt++) {
        #pragma unroll
        for (int hf = 0; hf < 2; hf++) {
            int px_local = mt*16 + gid + hf*8;
            int py = ty0 + w;
            int px = tx0 + px_local;
            size_t pidx = (size_t)b * CHW + (size_t)py * Ww + px;
            uint32_t* rp = rowbase + ((size_t)b * HW + (size_t)py * Ww + px) * 32;
            #pragma unroll
            for (int n = 0; n < 4; n++) {
                int cl = n*8 + 2*tig;
                int co = half*32 + cl;
                float a0 = acc[mt][n][hf*2]     + g_bcomb[co];
                float a1 = acc[mt][n][hf*2 + 1] + g_bcomb[co+1];
                float i0 = g_invtau[co], i1 = g_invtau[co+1];
                float c0 = fast_tanh(a0), c1 = fast_tanh(a1);
                if (half == 0) {
                    float h0 = (i0 < 1.f) ? he[pidx + (size_t)cl * HW]     : 0.f;
                    float h1 = (i1 < 1.f) ? he[pidx + (size_t)(cl+1) * HW] : 0.f;
                    float v0 = (1.f - i0)*h0 + i0*c0;
                    float v1 = (1.f - i1)*h1 + i1*c1;
                    out[(size_t)NTOT + pidx + (size_t)cl * HW]     = v0;
                    out[(size_t)NTOT + pidx + (size_t)(cl+1) * HW] = v1;
                    unsigned short h0b, l0b, h1b, l1b;
                    bf16split(v0, h0b, l0b);
                    bf16split(v1, h1b, l1b);
                    int widx = cl >> 1;
                    rp[widx]      = (uint32_t)h0b | ((uint32_t)h1b << 16);
                    rp[16 + widx] = (uint32_t)l0b | ((uint32_t)l1b << 16);
                } else {
                    float h0 = (i0 < 1.f) ? hi[pidx + (size_t)cl * HW]     : 0.f;
                    float h1 = (i1 < 1.f) ? hi[pidx + (size_t)(cl+1) * HW] : 0.f;
                    out[(size_t)2*NTOT + pidx + (size_t)cl * HW]     = (1.f - i0)*h0 + i0*c0;
                    out[(size_t)2*NTOT + pidx + (size_t)(cl+1) * HW] = (1.f - i1)*h1 + i1*c1;
                }
            }
        }
    }
}

// ---------------- out kernel ----------------
__global__ void __launch_bounds__(THREADS, 2)
out_kernel(float* __restrict__ out)
{
    extern __shared__ char sm[];
    const uint32_t smb = smem_u32(sm);
    const int tid  = threadIdx.x;
    const int w    = tid >> 5;
    const int lane = tid & 31;
    const int gid  = lane >> 2;
    const int tig  = lane & 3;
    const int b    = blockIdx.z;
    const int ty0  = blockIdx.y * 8;
    const int tx0  = blockIdx.x * 32;

    float acc[2][4][4];
    #pragma unroll
    for (int mt = 0; mt < 2; mt++)
        #pragma unroll
        for (int n = 0; n < 4; n++)
            #pragma unroll
            for (int q = 0; q < 4; q++) acc[mt][n][q] = 0.f;

    const int hbase = (w + 1) * 34 + 1;
    const uint32_t laneA0 = smb + A_OFF + (uint32_t)(hbase + (lane & 15)) * RS
                          + (uint32_t)((lane >> 4) << 4);
    const uint32_t laneA1 = laneA0 + 16u*RS;
    const uint32_t laneB  = smb + B_OFF
                          + (uint32_t)((((lane >> 4) & 1)*8 + (lane & 7))) * RS
                          + (uint32_t)(((lane >> 3) & 1) << 4);

    {
        const char* bsrc = (const char*)g_Bout;
        for (int i = tid; i < B_SZ/16; i += THREADS)
            cp16(smb + B_OFF + (uint32_t)i*16, bsrc + (size_t)i*16);
    }
    stage_A(sm, smb, 3, b, ty0, tx0, tid);
    CP_COMMIT();
    CP_WAIT0();
    __syncthreads();

    conv_tap_loop(acc, laneA0, laneA1, laneB);

    #pragma unroll
    for (int mt = 0; mt < 2; mt++) {
        #pragma unroll
        for (int hf = 0; hf < 2; hf++) {
            int px_local = mt*16 + gid + hf*8;
            int py = ty0 + w;
            int px = tx0 + px_local;
            size_t pidx = (size_t)b * CHW + (size_t)py * Ww + px;
            #pragma unroll
            for (int n = 0; n < 4; n++) {
                #pragma unroll
                for (int q = 0; q < 2; q++) {
                    int co  = n*8 + 2*tig + q;
                    float v = acc[mt][n][hf*2 + q] + g_bout[co];
                    out[pidx + (size_t)co * HW] = fast_tanh(v);
                }
            }
        }
    }
}

extern "C" void kernel_launch(void* const* d_in, const int* in_sizes, int n_in,
                              void* d_out, int out_size)
{
    (void)in_sizes; (void)n_in; (void)out_size;
    const float* x  = (const float*)d_in[0];
    const float* he = (const float*)d_in[1];
    const float* hi = (const float*)d_in[2];
    float* out = (float*)d_out;

    cudaFuncSetAttribute(state_kernel, cudaFuncAttributeMaxDynamicSharedMemorySize, SMEM_T);
    cudaFuncSetAttribute(out_kernel,   cudaFuncAttributeMaxDynamicSharedMemorySize, SMEM_T);

    prep_kernel<<<252, 256>>>(
        (const float*)d_in[3],  (const float*)d_in[4],
        (const float*)d_in[5],  (const float*)d_in[6],
        (const float*)d_in[7],  (const float*)d_in[8],
        (const float*)d_in[9],  (const float*)d_in[10],
        (const float*)d_in[11], (const float*)d_in[12],
        (const float*)d_in[13], (const float*)d_in[14],
        (const float*)d_in[15], (const float*)d_in[16],
        (const float*)d_in[17], (const float*)d_in[18]);

    convert_kernel<<<(3*Bn*HW)/256, 256>>>(x, he, hi);

    dim3 gs(4, 16, Bn*2);   // x-tiles, y-tiles, batch x co-half
    state_kernel<<<gs, THREADS, SMEM_T>>>(he, hi, out);
    dim3 go(4, 16, Bn);
    out_kernel<<<go, THREADS, SMEM_T>>>(out);
}